// round 11
// baseline (speedup 1.0000x reference)
#include <cuda_runtime.h>
#include <cuda_bf16.h>
#include <cstdint>

// Problem constants
constexpr int B  = 4;
constexpr int S  = 2048;
constexpr int D  = 1024;
constexpr int H  = 16;
constexpr int DK = 64;
constexpr int M_TOTAL = B * S;   // 8192

constexpr int KA = 2 * D;        // 2048 (hi | lo)
constexpr size_t ACT_SLOT = (size_t)M_TOTAL * KA;
constexpr size_t W_SLOT   = (size_t)D * KA;
constexpr size_t HEAD_SLOT = (size_t)B * H * S * 128;

// ---------------------------------------------------------------------------
// Device scratch (allocation-free rule)
// ---------------------------------------------------------------------------
__device__ __nv_bfloat16 g_ab3[3 * ACT_SLOT];    // q,k,v acts; slot0 reused for attn out
__device__ __nv_bfloat16 g_wb4[4 * W_SLOT];      // w_q,w_k,w_v,w_o
__device__ __nv_bfloat16 g_qkvb[3 * HEAD_SLOT];  // Q,K,V head-major hi/lo

// ---------------------------------------------------------------------------
// helpers
// ---------------------------------------------------------------------------
__device__ __forceinline__ uint32_t smem_u32(const void* p) {
    uint32_t a;
    asm("{ .reg .u64 t; cvta.to.shared.u64 t, %1; cvt.u32.u64 %0, t; }"
        : "=r"(a) : "l"(p));
    return a;
}
__device__ __forceinline__ void cp16(uint32_t s, const void* g) {
    asm volatile("cp.async.cg.shared.global [%0], [%1], 16;" :: "r"(s), "l"(g));
}
__device__ __forceinline__ void ldmatrix_x4(uint32_t& r0, uint32_t& r1,
                                            uint32_t& r2, uint32_t& r3, uint32_t a) {
    asm volatile("ldmatrix.sync.aligned.m8n8.x4.shared.b16 {%0,%1,%2,%3}, [%4];"
                 : "=r"(r0), "=r"(r1), "=r"(r2), "=r"(r3) : "r"(a));
}
__device__ __forceinline__ void ldmatrix_x4_t(uint32_t& r0, uint32_t& r1,
                                              uint32_t& r2, uint32_t& r3, uint32_t a) {
    asm volatile("ldmatrix.sync.aligned.m8n8.x4.trans.shared.b16 {%0,%1,%2,%3}, [%4];"
                 : "=r"(r0), "=r"(r1), "=r"(r2), "=r"(r3) : "r"(a));
}
__device__ __forceinline__ void mma_bf16(float* c, const uint32_t* a, const uint32_t* b) {
    asm volatile("mma.sync.aligned.m16n8k16.row.col.f32.bf16.bf16.f32 "
                 "{%0,%1,%2,%3},{%4,%5,%6,%7},{%8,%9},{%0,%1,%2,%3};"
                 : "+f"(c[0]), "+f"(c[1]), "+f"(c[2]), "+f"(c[3])
                 : "r"(a[0]), "r"(a[1]), "r"(a[2]), "r"(a[3]), "r"(b[0]), "r"(b[1]));
}
__device__ __forceinline__ uint32_t cvt2bf(float phi, float plo) {
    uint32_t r;
    asm("cvt.rn.bf16x2.f32 %0, %1, %2;" : "=r"(r) : "f"(phi), "f"(plo));
    return r;
}
__device__ __forceinline__ float bf_lo(uint32_t p) { return __uint_as_float(p << 16); }
__device__ __forceinline__ float bf_hi(uint32_t p) { return __uint_as_float(p & 0xFFFF0000u); }

// ---------------------------------------------------------------------------
// Conversion kernels: fp32 [R, D] -> bf16 hi/lo [R, 2D]
// ---------------------------------------------------------------------------
__device__ __forceinline__ void conv_body(const float* __restrict__ X,
                                          __nv_bfloat16* __restrict__ Yb)
{
    const int i = (blockIdx.x * 256 + threadIdx.x) * 4;
    float4 x = *(const float4*)(X + i);
    const int row = i >> 10;
    const int col = i & (D - 1);
    float xv[4] = {x.x, x.y, x.z, x.w};
    uint32_t hp[2], lp[2];
#pragma unroll
    for (int j = 0; j < 2; j++) {
        hp[j] = cvt2bf(xv[2*j+1], xv[2*j]);
        lp[j] = cvt2bf(xv[2*j+1] - bf_hi(hp[j]), xv[2*j] - bf_lo(hp[j]));
    }
    uint32_t* ph = (uint32_t*)(Yb + (size_t)row * KA + col);
    uint32_t* pl = (uint32_t*)(Yb + (size_t)row * KA + D + col);
    ph[0] = hp[0]; ph[1] = hp[1];
    pl[0] = lp[0]; pl[1] = lp[1];
}

__global__ __launch_bounds__(256)
void conv_acts(const float* __restrict__ q, const float* __restrict__ k,
               const float* __restrict__ v, __nv_bfloat16* __restrict__ Y3)
{
    const int z = blockIdx.y;
    const float* X = (z == 0) ? q : (z == 1) ? k : v;
    conv_body(X, Y3 + (size_t)z * ACT_SLOT);
}

__global__ __launch_bounds__(256)
void conv_ws(const float* __restrict__ wq, const float* __restrict__ wk,
             const float* __restrict__ wv, const float* __restrict__ wo,
             __nv_bfloat16* __restrict__ Y4)
{
    const int z = blockIdx.y;
    const float* X = (z == 0) ? wq : (z == 1) ? wk : (z == 2) ? wv : wo;
    conv_body(X, Y4 + (size_t)z * W_SLOT);
}

// ---------------------------------------------------------------------------
// bf16 mma.sync GEMM, hi/lo split (3 products), 3-stage pipeline.
// CTA tile 128x64, 256 threads / 8 warps, warp tile 32x32 (acc = 32 regs)
// -> natural occupancy 2 CTAs/SM without spills.
// ---------------------------------------------------------------------------
constexpr int BKC = 32;
constexpr int NCH = D / BKC;                // 32 chunks
constexpr int A_TILE_B = 128 * BKC * 2;     // 8192 B (one of hi/lo)
constexpr int W_TILE_B = 64 * BKC * 2;      // 4096 B
constexpr int STAGE_B  = 2 * A_TILE_B + 2 * W_TILE_B;   // 24 KB
constexpr int GEMM_SMEM = 3 * STAGE_B;      // 72 KB

__global__ __launch_bounds__(256, 2)
void gemm_tc(const __nv_bfloat16* __restrict__ Ab, const __nv_bfloat16* __restrict__ Wb,
             const float* __restrict__ bq, const float* __restrict__ bk,
             const float* __restrict__ bv,
             float* __restrict__ Yf, __nv_bfloat16* __restrict__ Yb, int mode)
{
    extern __shared__ char smem[];
    const uint32_t sbase = smem_u32(smem);
    const int tid  = threadIdx.x;
    const int wid  = tid >> 5;
    const int lane = tid & 31;
    const int z = blockIdx.z;
    const int m0 = blockIdx.y * 128;
    const int n0 = blockIdx.x * 64;
    const int wm = (wid >> 1) * 32;         // 4 m-warps x 32 rows
    const int wn = (wid & 1) * 32;          // 2 n-warps x 32 cols

    Ab += (size_t)z * ACT_SLOT;
    Wb += (size_t)z * W_SLOT;
    const float* bias = (z == 0) ? bq : (z == 1) ? bk : bv;
    const float scale = (mode == 1 && z == 0) ? 0.125f : 1.0f;
    __nv_bfloat16* Ybz = Yb + (size_t)z * HEAD_SLOT;

    float acc[2][4][4];
#pragma unroll
    for (int mi = 0; mi < 2; mi++)
#pragma unroll
        for (int ni = 0; ni < 4; ni++)
#pragma unroll
            for (int r = 0; r < 4; r++) acc[mi][ni][r] = 0.f;

    // cooperative load: A via (tid>>1, 2 quads), W via (tid>>2, 1 quad)
    const int lrA = tid >> 1, lhA = tid & 1;
    const int lrW = tid >> 2, lqW = tid & 3;

    auto load_chunk = [&](int c) {
        const uint32_t stage = sbase + (uint32_t)(c % 3) * STAGE_B;
        const int kc = c * BKC;
        const __nv_bfloat16* ga = Ab + (size_t)(m0 + lrA) * KA + kc;
        const __nv_bfloat16* gw = Wb + (size_t)(n0 + lrW) * KA + kc;
        const int mgA = lrA >> 3, r8A = lrA & 7;
#pragma unroll
        for (int j = 0; j < 2; j++) {
            const int kg = lhA * 2 + j;
            const uint32_t so = (uint32_t)((kg * 16 + mgA) * 128 + r8A * 16);
            cp16(stage + so, ga + kg * 8);                       // A hi
            cp16(stage + A_TILE_B + so, ga + D + kg * 8);        // A lo
        }
        const int ngW = lrW >> 3, r8W = lrW & 7;
        const uint32_t sow = (uint32_t)((lqW * 8 + ngW) * 128 + r8W * 16);
        cp16(stage + 2 * A_TILE_B + sow, gw + lqW * 8);               // W hi
        cp16(stage + 2 * A_TILE_B + W_TILE_B + sow, gw + D + lqW * 8);// W lo
        asm volatile("cp.async.commit_group;");
    };

    load_chunk(0);
    load_chunk(1);

    const int gA = lane >> 3;
    const int rA = lane & 7;

#pragma unroll 1
    for (int c = 0; c < NCH; c++) {
        if (c + 1 < NCH) asm volatile("cp.async.wait_group 1;" ::: "memory");
        else             asm volatile("cp.async.wait_group 0;" ::: "memory");
        __syncthreads();
        if (c + 2 < NCH) load_chunk(c + 2);

        const uint32_t stage = sbase + (uint32_t)(c % 3) * STAGE_B;
        const uint32_t ahiB = stage;
        const uint32_t aloB = stage + A_TILE_B;
        const uint32_t whiB = stage + 2 * A_TILE_B;
        const uint32_t wloB = whiB + W_TILE_B;

#pragma unroll
        for (int ks = 0; ks < 2; ks++) {
            const int kg0 = ks * 2;
            uint32_t bhi[4][2], blo[4][2];
#pragma unroll
            for (int np = 0; np < 2; np++) {
                const int ng  = (wn >> 3) + 2 * np + (gA >> 1);
                const int kgB = kg0 + (gA & 1);
                const uint32_t off = (uint32_t)((kgB * 8 + ng) * 128 + rA * 16);
                ldmatrix_x4(bhi[2*np][0], bhi[2*np][1], bhi[2*np+1][0], bhi[2*np+1][1],
                            whiB + off);
                ldmatrix_x4(blo[2*np][0], blo[2*np][1], blo[2*np+1][0], blo[2*np+1][1],
                            wloB + off);
            }
#pragma unroll
            for (int mi = 0; mi < 2; mi++) {
                uint32_t ahi[4], alo[4];
                const int mgB = (wm >> 3) + mi * 2 + (gA & 1);
                const int kgB = kg0 + (gA >> 1);
                const uint32_t off = (uint32_t)((kgB * 16 + mgB) * 128 + rA * 16);
                ldmatrix_x4(ahi[0], ahi[1], ahi[2], ahi[3], ahiB + off);
                ldmatrix_x4(alo[0], alo[1], alo[2], alo[3], aloB + off);
#pragma unroll
                for (int ni = 0; ni < 4; ni++) {
                    mma_bf16(acc[mi][ni], ahi, bhi[ni]);
                    mma_bf16(acc[mi][ni], ahi, blo[ni]);
                    mma_bf16(acc[mi][ni], alo, bhi[ni]);
                }
            }
        }
    }

    // epilogue
#pragma unroll
    for (int mi = 0; mi < 2; mi++) {
#pragma unroll
        for (int ni = 0; ni < 4; ni++) {
            const int m = m0 + wm + mi * 16 + (lane >> 2);
            const int n = n0 + wn + ni * 8 + (lane & 3) * 2;
            const float b0 = __ldg(&bias[n]);
            const float b1 = __ldg(&bias[n + 1]);
            const float v00 = (acc[mi][ni][0] + b0) * scale;
            const float v01 = (acc[mi][ni][1] + b1) * scale;
            const float v10 = (acc[mi][ni][2] + b0) * scale;
            const float v11 = (acc[mi][ni][3] + b1) * scale;
            if (mode == 1) {
                const int h  = n >> 6;
                const int dk = n & (DK - 1);
#pragma unroll
                for (int rr = 0; rr < 2; rr++) {
                    const int mr = m + rr * 8;
                    const float p0 = rr ? v10 : v00;
                    const float p1 = rr ? v11 : v01;
                    const int bb = mr >> 11;
                    const int s  = mr & (S - 1);
                    __nv_bfloat16* base =
                        Ybz + (((size_t)bb * H + h) * S + s) * 128 + dk;
                    const uint32_t hp = cvt2bf(p1, p0);
                    const uint32_t lp = cvt2bf(p1 - bf_hi(hp), p0 - bf_lo(hp));
                    *(uint32_t*)(base)      = hp;
                    *(uint32_t*)(base + 64) = lp;
                }
            } else {
                *(float2*)(Yf + (size_t)m * D + n)       = make_float2(v00, v01);
                *(float2*)(Yf + (size_t)(m + 8) * D + n) = make_float2(v10, v11);
            }
        }
    }
}

// ---------------------------------------------------------------------------
// Tensor-core flash attention (bf16 hi/lo, 3 products each GEMM).
// ATK=32 key tiles, occupancy 2, 3-stage KV pipeline (stage 2 = recycled Q
// smem). Unchanged from round 10 (measured 775 us).
// ---------------------------------------------------------------------------
constexpr int ATQ = 128;
constexpr int ATK = 32;
constexpr int NKT = S / ATK;             // 64
constexpr int Q_SMEM = ATQ * 128 * 2;    // 32768
constexpr int KT_SMEM = ATK * 128 * 2;   // 8192
constexpr int AT_STAGE = 2 * KT_SMEM;    // 16384
constexpr int ATT_SMEM = Q_SMEM + 2 * AT_STAGE;  // 65536

__global__ __launch_bounds__(256, 2)
void attn_mma(const __nv_bfloat16* __restrict__ QKV, const int* __restrict__ mask,
              __nv_bfloat16* __restrict__ Aout)
{
    extern __shared__ char smem[];
    const uint32_t sq  = smem_u32(smem);
    const uint32_t skv = sq + Q_SMEM;
    const int tid = threadIdx.x, wid = tid >> 5, lane = tid & 31;
    const int b = blockIdx.z, h = blockIdx.y;
    const int q0blk = blockIdx.x * ATQ;
    const size_t headoff = ((size_t)(b * H + h) * S) * 128;
    const __nv_bfloat16* Qg = QKV + headoff + (size_t)q0blk * 128;
    const __nv_bfloat16* Kg = QKV + HEAD_SLOT + headoff;
    const __nv_bfloat16* Vg = QKV + 2 * HEAD_SLOT + headoff;
    const int wm = wid * 16;

    auto stage_of = [&](int c) -> uint32_t {
        const int s3 = c % 3;
        return (s3 == 0) ? skv : (s3 == 1) ? (skv + AT_STAGE) : sq;
    };

    auto load_kv = [&](int c) {
        const uint32_t st = stage_of(c);
        const int r = tid & 31, g = tid >> 5;
        const __nv_bfloat16* ks = Kg + (size_t)(c * ATK + r) * 128;
        const __nv_bfloat16* vs = Vg + (size_t)(c * ATK + r) * 128;
#pragma unroll
        for (int j = 0; j < 2; j++) {
            const int cg = g * 2 + j;
            const uint32_t so = (uint32_t)(((cg * 4 + (r >> 3)) * 8 + (r & 7)) * 16);
            cp16(st + so, ks + cg * 8);
            cp16(st + KT_SMEM + so, vs + cg * 8);
        }
        asm volatile("cp.async.commit_group;");
    };

    // Q tile load (grouped with stage-0 commit)
    {
        const int r = tid & 127, half = tid >> 7;
        const __nv_bfloat16* src = Qg + (size_t)r * 128;
#pragma unroll
        for (int j = 0; j < 8; j++) {
            const int cg = half * 8 + j;
            const uint32_t so = (uint32_t)(((cg * 16 + (r >> 3)) * 8 + (r & 7)) * 16);
            cp16(sq + so, src + cg * 8);
        }
    }
    load_kv(0);
    load_kv(1);

    asm volatile("cp.async.wait_group 1;" ::: "memory");
    __syncthreads();

    const int gA = lane >> 3, rA = lane & 7;

    // Q fragments -> registers (sq becomes KV stage 2 afterwards)
    uint32_t qhi[4][4], qlo[4][4];
#pragma unroll
    for (int kk = 0; kk < 4; kk++) {
        const int rg = (wm >> 3) + (gA & 1);
        const int cgh = 2 * kk + (gA >> 1);
        ldmatrix_x4(qhi[kk][0], qhi[kk][1], qhi[kk][2], qhi[kk][3],
                    sq + (uint32_t)(((cgh * 16 + rg) * 8 + rA) * 16));
        ldmatrix_x4(qlo[kk][0], qlo[kk][1], qlo[kk][2], qlo[kk][3],
                    sq + (uint32_t)((((cgh + 8) * 16 + rg) * 8 + rA) * 16));
    }
    __syncthreads();

    float o[8][4];
#pragma unroll
    for (int ng = 0; ng < 8; ng++)
#pragma unroll
        for (int r = 0; r < 4; r++) o[ng][r] = 0.f;
    float m0 = -1e30f, m1 = -1e30f, l0 = 0.f, l1 = 0.f;

    const int r0l = lane >> 2, c0l = (lane & 3) * 2;
    const int qg0 = q0blk + wm + r0l;
    const int* mr0 = mask + ((size_t)b * S + qg0) * S + c0l;
    const int* mr1 = mr0 + 8 * S;

#pragma unroll 1
    for (int c = 0; c < NKT; c++) {
        if (c + 1 < NKT) asm volatile("cp.async.wait_group 1;" ::: "memory");
        else             asm volatile("cp.async.wait_group 0;" ::: "memory");
        __syncthreads();
        if (c + 2 < NKT) load_kv(c + 2);

        const uint32_t kb_ = stage_of(c);
        const uint32_t vb_ = kb_ + KT_SMEM;

        // ---- scores: 32 keys -> sc[4][4] ----
        float sc[4][4];
#pragma unroll
        for (int ng = 0; ng < 4; ng++)
#pragma unroll
            for (int r = 0; r < 4; r++) sc[ng][r] = 0.f;

#pragma unroll
        for (int ng = 0; ng < 4; ng += 2) {
#pragma unroll
            for (int kk = 0; kk < 4; kk++) {
                uint32_t kh[4], kl[4];
                const int rg = ng + (gA >> 1);
                const int cg = 2 * kk + (gA & 1);
                ldmatrix_x4(kh[0], kh[1], kh[2], kh[3],
                            kb_ + (uint32_t)(((cg * 4 + rg) * 8 + rA) * 16));
                ldmatrix_x4(kl[0], kl[1], kl[2], kl[3],
                            kb_ + (uint32_t)((((cg + 8) * 4 + rg) * 8 + rA) * 16));
                mma_bf16(sc[ng],     qhi[kk], kh + 0);
                mma_bf16(sc[ng],     qhi[kk], kl + 0);
                mma_bf16(sc[ng],     qlo[kk], kh + 0);
                mma_bf16(sc[ng + 1], qhi[kk], kh + 2);
                mma_bf16(sc[ng + 1], qhi[kk], kl + 2);
                mma_bf16(sc[ng + 1], qlo[kk], kh + 2);
            }
        }

        // ---- mask ----
        const int koff = c * ATK;
#pragma unroll
        for (int ng = 0; ng < 4; ng++) {
            const int2 mA = *(const int2*)(mr0 + koff + ng * 8);
            const int2 mB = *(const int2*)(mr1 + koff + ng * 8);
            if (mA.x == 0) sc[ng][0] = -1e9f;
            if (mA.y == 0) sc[ng][1] = -1e9f;
            if (mB.x == 0) sc[ng][2] = -1e9f;
            if (mB.y == 0) sc[ng][3] = -1e9f;
        }

        // ---- online softmax ----
        float mx0 = sc[0][0], mx1 = sc[0][2];
#pragma unroll
        for (int ng = 0; ng < 4; ng++) {
            mx0 = fmaxf(mx0, fmaxf(sc[ng][0], sc[ng][1]));
            mx1 = fmaxf(mx1, fmaxf(sc[ng][2], sc[ng][3]));
        }
        mx0 = fmaxf(mx0, __shfl_xor_sync(0xffffffffu, mx0, 1));
        mx0 = fmaxf(mx0, __shfl_xor_sync(0xffffffffu, mx0, 2));
        mx1 = fmaxf(mx1, __shfl_xor_sync(0xffffffffu, mx1, 1));
        mx1 = fmaxf(mx1, __shfl_xor_sync(0xffffffffu, mx1, 2));

        const float mn0 = fmaxf(m0, mx0);
        const float mn1 = fmaxf(m1, mx1);
        const float cr0 = __expf(m0 - mn0);
        const float cr1 = __expf(m1 - mn1);
#pragma unroll
        for (int ng = 0; ng < 8; ng++) {
            o[ng][0] *= cr0; o[ng][1] *= cr0;
            o[ng][2] *= cr1; o[ng][3] *= cr1;
        }

        // ---- exp + P·V fused, kp-outer ----
        float rs0 = 0.f, rs1 = 0.f;
#pragma unroll
        for (int kp = 0; kp < 2; kp++) {
            const float p00 = __expf(sc[2*kp][0]   - mn0);
            const float p01 = __expf(sc[2*kp][1]   - mn0);
            const float p10 = __expf(sc[2*kp][2]   - mn1);
            const float p11 = __expf(sc[2*kp][3]   - mn1);
            const float p20 = __expf(sc[2*kp+1][0] - mn0);
            const float p21 = __expf(sc[2*kp+1][1] - mn0);
            const float p30 = __expf(sc[2*kp+1][2] - mn1);
            const float p31 = __expf(sc[2*kp+1][3] - mn1);
            rs0 += (p00 + p01) + (p20 + p21);
            rs1 += (p10 + p11) + (p30 + p31);
            uint32_t phi[4], plo[4];
            phi[0] = cvt2bf(p01, p00);
            phi[1] = cvt2bf(p11, p10);
            phi[2] = cvt2bf(p21, p20);
            phi[3] = cvt2bf(p31, p30);
            plo[0] = cvt2bf(p01 - bf_hi(phi[0]), p00 - bf_lo(phi[0]));
            plo[1] = cvt2bf(p11 - bf_hi(phi[1]), p10 - bf_lo(phi[1]));
            plo[2] = cvt2bf(p21 - bf_hi(phi[2]), p20 - bf_lo(phi[2]));
            plo[3] = cvt2bf(p31 - bf_hi(phi[3]), p30 - bf_lo(phi[3]));

            const int rg = 2 * kp + (gA & 1);
#pragma unroll
            for (int ng = 0; ng < 8; ng += 2) {
                const int cg = ng + (gA >> 1);
                uint32_t vh[4], vl[4];
                ldmatrix_x4_t(vh[0], vh[1], vh[2], vh[3],
                              vb_ + (uint32_t)(((cg * 4 + rg) * 8 + rA) * 16));
                ldmatrix_x4_t(vl[0], vl[1], vl[2], vl[3],
                              vb_ + (uint32_t)((((cg + 8) * 4 + rg) * 8 + rA) * 16));
                mma_bf16(o[ng],     phi, vh + 0);
                mma_bf16(o[ng],     phi, vl + 0);
                mma_bf16(o[ng],     plo, vh + 0);
                mma_bf16(o[ng + 1], phi, vh + 2);
                mma_bf16(o[ng + 1], phi, vl + 2);
                mma_bf16(o[ng + 1], plo, vh + 2);
            }
        }
        rs0 += __shfl_xor_sync(0xffffffffu, rs0, 1);
        rs0 += __shfl_xor_sync(0xffffffffu, rs0, 2);
        rs1 += __shfl_xor_sync(0xffffffffu, rs1, 1);
        rs1 += __shfl_xor_sync(0xffffffffu, rs1, 2);
        l0 = l0 * cr0 + rs0;
        l1 = l1 * cr1 + rs1;
        m0 = mn0; m1 = mn1;
    }

    // ---- epilogue: bf16 hi/lo straight into the O-proj A buffer ----
    const float inv0 = 1.f / l0;
    const float inv1 = 1.f / l1;
    __nv_bfloat16* dst0 = Aout + (size_t)(b * S + qg0) * KA + h * DK + c0l;
    __nv_bfloat16* dst1 = dst0 + (size_t)8 * KA;
#pragma unroll
    for (int ng = 0; ng < 8; ng++) {
        const float x0 = o[ng][0] * inv0, x1 = o[ng][1] * inv0;
        const float y0 = o[ng][2] * inv1, y1 = o[ng][3] * inv1;
        const uint32_t hx = cvt2bf(x1, x0);
        const uint32_t lx = cvt2bf(x1 - bf_hi(hx), x0 - bf_lo(hx));
        const uint32_t hy = cvt2bf(y1, y0);
        const uint32_t ly = cvt2bf(y1 - bf_hi(hy), y0 - bf_lo(hy));
        *(uint32_t*)(dst0 + ng * 8)     = hx;
        *(uint32_t*)(dst0 + D + ng * 8) = lx;
        *(uint32_t*)(dst1 + ng * 8)     = hy;
        *(uint32_t*)(dst1 + D + ng * 8) = ly;
    }
}

// ---------------------------------------------------------------------------
// launch
// ---------------------------------------------------------------------------
extern "C" void kernel_launch(void* const* d_in, const int* in_sizes, int n_in,
                              void* d_out, int out_size)
{
    const float* query = (const float*)d_in[0];
    const float* key_  = (const float*)d_in[1];
    const float* value = (const float*)d_in[2];
    const int*   amask = (const int*)  d_in[3];
    const float* w_q = (const float*)d_in[4];
    const float* b_q = (const float*)d_in[5];
    const float* w_k = (const float*)d_in[6];
    const float* b_k = (const float*)d_in[7];
    const float* w_v = (const float*)d_in[8];
    const float* b_v = (const float*)d_in[9];
    const float* w_o = (const float*)d_in[10];
    const float* b_o = (const float*)d_in[11];
    float* out = (float*)d_out;

    __nv_bfloat16 *gab3, *gwb4, *gqkvb;
    cudaGetSymbolAddress((void**)&gab3,  g_ab3);
    cudaGetSymbolAddress((void**)&gwb4,  g_wb4);
    cudaGetSymbolAddress((void**)&gqkvb, g_qkvb);

    cudaFuncSetAttribute(gemm_tc, cudaFuncAttributeMaxDynamicSharedMemorySize, GEMM_SMEM);
    cudaFuncSetAttribute(attn_mma, cudaFuncAttributeMaxDynamicSharedMemorySize, ATT_SMEM);

    conv_acts<<<dim3(M_TOTAL * D / (4 * 256), 3), 256>>>(query, key_, value, gab3);
    conv_ws  <<<dim3(D * D / (4 * 256), 4), 256>>>(w_q, w_k, w_v, w_o, gwb4);

    gemm_tc<<<dim3(D / 64, M_TOTAL / 128, 3), 256, GEMM_SMEM>>>(
        gab3, gwb4, b_q, b_k, b_v, nullptr, gqkvb, 1);

    attn_mma<<<dim3(S / ATQ, H, B), 256, ATT_SMEM>>>(gqkvb, amask, gab3);

    gemm_tc<<<dim3(D / 64, M_TOTAL / 128, 1), 256, GEMM_SMEM>>>(
        gab3, gwb4 + 3 * W_SLOT, b_o, b_o, b_o, out, nullptr, 0);
}

// round 13
// speedup vs baseline: 1.1064x; 1.1064x over previous
#include <cuda_runtime.h>
#include <cuda_bf16.h>
#include <cstdint>

// Problem constants
constexpr int B  = 4;
constexpr int S  = 2048;
constexpr int D  = 1024;
constexpr int H  = 16;
constexpr int DK = 64;
constexpr int M_TOTAL = B * S;   // 8192

constexpr int KA = 2 * D;        // 2048 (hi | lo)
constexpr size_t ACT_SLOT = (size_t)M_TOTAL * KA;
constexpr size_t W_SLOT   = (size_t)D * KA;
constexpr size_t HEAD_SLOT = (size_t)B * H * S * 128;

// ---------------------------------------------------------------------------
// Device scratch (allocation-free rule)
// ---------------------------------------------------------------------------
__device__ __nv_bfloat16 g_ab3[3 * ACT_SLOT];    // q,k,v acts; slot0 reused for attn out
__device__ __nv_bfloat16 g_wb4[4 * W_SLOT];      // w_q,w_k,w_v,w_o
__device__ __nv_bfloat16 g_qkvb[3 * HEAD_SLOT];  // Q,K,V head-major hi/lo

// ---------------------------------------------------------------------------
// helpers
// ---------------------------------------------------------------------------
__device__ __forceinline__ uint32_t smem_u32(const void* p) {
    uint32_t a;
    asm("{ .reg .u64 t; cvta.to.shared.u64 t, %1; cvt.u32.u64 %0, t; }"
        : "=r"(a) : "l"(p));
    return a;
}
__device__ __forceinline__ void cp16(uint32_t s, const void* g) {
    asm volatile("cp.async.cg.shared.global [%0], [%1], 16;" :: "r"(s), "l"(g));
}
__device__ __forceinline__ void ldmatrix_x4(uint32_t& r0, uint32_t& r1,
                                            uint32_t& r2, uint32_t& r3, uint32_t a) {
    asm volatile("ldmatrix.sync.aligned.m8n8.x4.shared.b16 {%0,%1,%2,%3}, [%4];"
                 : "=r"(r0), "=r"(r1), "=r"(r2), "=r"(r3) : "r"(a));
}
__device__ __forceinline__ void ldmatrix_x4_t(uint32_t& r0, uint32_t& r1,
                                              uint32_t& r2, uint32_t& r3, uint32_t a) {
    asm volatile("ldmatrix.sync.aligned.m8n8.x4.trans.shared.b16 {%0,%1,%2,%3}, [%4];"
                 : "=r"(r0), "=r"(r1), "=r"(r2), "=r"(r3) : "r"(a));
}
__device__ __forceinline__ void mma_bf16(float* c, const uint32_t* a, const uint32_t* b) {
    asm volatile("mma.sync.aligned.m16n8k16.row.col.f32.bf16.bf16.f32 "
                 "{%0,%1,%2,%3},{%4,%5,%6,%7},{%8,%9},{%0,%1,%2,%3};"
                 : "+f"(c[0]), "+f"(c[1]), "+f"(c[2]), "+f"(c[3])
                 : "r"(a[0]), "r"(a[1]), "r"(a[2]), "r"(a[3]), "r"(b[0]), "r"(b[1]));
}
__device__ __forceinline__ uint32_t cvt2bf(float phi, float plo) {
    uint32_t r;
    asm("cvt.rn.bf16x2.f32 %0, %1, %2;" : "=r"(r) : "f"(phi), "f"(plo));
    return r;
}
__device__ __forceinline__ float bf_lo(uint32_t p) { return __uint_as_float(p << 16); }
__device__ __forceinline__ float bf_hi(uint32_t p) { return __uint_as_float(p & 0xFFFF0000u); }

// ---------------------------------------------------------------------------
// Conversion kernels: fp32 [R, D] -> bf16 hi/lo [R, 2D]
// ---------------------------------------------------------------------------
__device__ __forceinline__ void conv_body(const float* __restrict__ X,
                                          __nv_bfloat16* __restrict__ Yb)
{
    const int i = (blockIdx.x * 256 + threadIdx.x) * 4;
    float4 x = *(const float4*)(X + i);
    const int row = i >> 10;
    const int col = i & (D - 1);
    float xv[4] = {x.x, x.y, x.z, x.w};
    uint32_t hp[2], lp[2];
#pragma unroll
    for (int j = 0; j < 2; j++) {
        hp[j] = cvt2bf(xv[2*j+1], xv[2*j]);
        lp[j] = cvt2bf(xv[2*j+1] - bf_hi(hp[j]), xv[2*j] - bf_lo(hp[j]));
    }
    uint32_t* ph = (uint32_t*)(Yb + (size_t)row * KA + col);
    uint32_t* pl = (uint32_t*)(Yb + (size_t)row * KA + D + col);
    ph[0] = hp[0]; ph[1] = hp[1];
    pl[0] = lp[0]; pl[1] = lp[1];
}

__global__ __launch_bounds__(256)
void conv_acts(const float* __restrict__ q, const float* __restrict__ k,
               const float* __restrict__ v, __nv_bfloat16* __restrict__ Y3)
{
    const int z = blockIdx.y;
    const float* X = (z == 0) ? q : (z == 1) ? k : v;
    conv_body(X, Y3 + (size_t)z * ACT_SLOT);
}

__global__ __launch_bounds__(256)
void conv_ws(const float* __restrict__ wq, const float* __restrict__ wk,
             const float* __restrict__ wv, const float* __restrict__ wo,
             __nv_bfloat16* __restrict__ Y4)
{
    const int z = blockIdx.y;
    const float* X = (z == 0) ? wq : (z == 1) ? wk : (z == 2) ? wv : wo;
    conv_body(X, Y4 + (size_t)z * W_SLOT);
}

// ---------------------------------------------------------------------------
// bf16 mma.sync GEMM — round-6 shape (measured best: ~830 us for 4 GEMMs).
// 128x128 CTA tile, 256 threads / 8 warps, warp tile 64x32 (acc 64 regs),
// 3-stage pipeline, single barrier per chunk, B loads via x4 batching.
// No register cap (natural ~157 regs, occupancy 1).
// ---------------------------------------------------------------------------
constexpr int BKC = 32;
constexpr int NCH = D / BKC;               // 32 chunks
constexpr int TILE_B  = 128 * BKC * 2;     // 8192 B
constexpr int STAGE_B = 4 * TILE_B;        // 32 KB
constexpr int GEMM_SMEM = 3 * STAGE_B;     // 96 KB

__global__ __launch_bounds__(256)
void gemm_tc(const __nv_bfloat16* __restrict__ Ab, const __nv_bfloat16* __restrict__ Wb,
             const float* __restrict__ bq, const float* __restrict__ bk,
             const float* __restrict__ bv,
             float* __restrict__ Yf, __nv_bfloat16* __restrict__ Yb, int mode)
{
    extern __shared__ char smem[];
    const uint32_t sbase = smem_u32(smem);
    const int tid  = threadIdx.x;
    const int wid  = tid >> 5;
    const int lane = tid & 31;
    const int z = blockIdx.z;
    const int m0 = blockIdx.y * 128;
    const int n0 = blockIdx.x * 128;
    const int wm = (wid >> 2) * 64;
    const int wn = (wid & 3) * 32;

    Ab += (size_t)z * ACT_SLOT;
    Wb += (size_t)z * W_SLOT;
    const float* bias = (z == 0) ? bq : (z == 1) ? bk : bv;
    const float scale = (mode == 1 && z == 0) ? 0.125f : 1.0f;
    __nv_bfloat16* Ybz = Yb + (size_t)z * HEAD_SLOT;

    float acc[4][4][4];
#pragma unroll
    for (int mi = 0; mi < 4; mi++)
#pragma unroll
        for (int ni = 0; ni < 4; ni++)
#pragma unroll
            for (int r = 0; r < 4; r++) acc[mi][ni][r] = 0.f;

    const int lr = tid >> 1;
    const int lh = tid & 1;

    auto load_chunk = [&](int c) {
        const uint32_t stage = sbase + (uint32_t)(c % 3) * STAGE_B;
        const int kc = c * BKC;
        const int mg = lr >> 3, r8 = lr & 7;
        const __nv_bfloat16* ga = Ab + (size_t)(m0 + lr) * KA + kc;
        const __nv_bfloat16* gw = Wb + (size_t)(n0 + lr) * KA + kc;
#pragma unroll
        for (int j = 0; j < 2; j++) {
            const int kg = lh * 2 + j;
            const uint32_t so = (uint32_t)((kg * 16 + mg) * 128 + r8 * 16);
            cp16(stage + 0 * TILE_B + so, ga + kg * 8);
            cp16(stage + 1 * TILE_B + so, ga + D + kg * 8);
            cp16(stage + 2 * TILE_B + so, gw + kg * 8);
            cp16(stage + 3 * TILE_B + so, gw + D + kg * 8);
        }
        asm volatile("cp.async.commit_group;");
    };

    load_chunk(0);
    load_chunk(1);

    const int gA = lane >> 3;
    const int rA = lane & 7;

    for (int c = 0; c < NCH; c++) {
        if (c + 1 < NCH) asm volatile("cp.async.wait_group 1;" ::: "memory");
        else             asm volatile("cp.async.wait_group 0;" ::: "memory");
        __syncthreads();
        if (c + 2 < NCH) load_chunk(c + 2);   // buffer consumed at iter c-1: safe

        const uint32_t stage = sbase + (uint32_t)(c % 3) * STAGE_B;
        const uint32_t ahiB = stage;
        const uint32_t aloB = stage + TILE_B;
        const uint32_t whiB = stage + 2 * TILE_B;
        const uint32_t wloB = stage + 3 * TILE_B;

#pragma unroll
        for (int ks = 0; ks < 2; ks++) {
            const int kg0 = ks * 2;
            uint32_t ahi[4][4], alo[4][4], bhi[4][2], blo[4][2];
#pragma unroll
            for (int mi = 0; mi < 4; mi++) {
                const int mgB = (wm >> 3) + mi * 2 + (gA & 1);
                const int kgB = kg0 + (gA >> 1);
                const uint32_t off = (uint32_t)((kgB * 16 + mgB) * 128 + rA * 16);
                ldmatrix_x4(ahi[mi][0], ahi[mi][1], ahi[mi][2], ahi[mi][3], ahiB + off);
                ldmatrix_x4(alo[mi][0], alo[mi][1], alo[mi][2], alo[mi][3], aloB + off);
            }
            // B: x4 loads batching (ni, ni+1) x (k-lo, k-hi)
#pragma unroll
            for (int np = 0; np < 2; np++) {
                const int ng  = (wn >> 3) + 2 * np + (gA >> 1);
                const int kgB = kg0 + (gA & 1);
                const uint32_t off = (uint32_t)((kgB * 16 + ng) * 128 + rA * 16);
                ldmatrix_x4(bhi[2*np][0], bhi[2*np][1], bhi[2*np+1][0], bhi[2*np+1][1],
                            whiB + off);
                ldmatrix_x4(blo[2*np][0], blo[2*np][1], blo[2*np+1][0], blo[2*np+1][1],
                            wloB + off);
            }
#pragma unroll
            for (int mi = 0; mi < 4; mi++)
#pragma unroll
                for (int ni = 0; ni < 4; ni++) {
                    mma_bf16(acc[mi][ni], ahi[mi], bhi[ni]);
                    mma_bf16(acc[mi][ni], ahi[mi], blo[ni]);
                    mma_bf16(acc[mi][ni], alo[mi], bhi[ni]);
                }
        }
    }

    // epilogue
#pragma unroll
    for (int mi = 0; mi < 4; mi++) {
#pragma unroll
        for (int ni = 0; ni < 4; ni++) {
            const int m = m0 + wm + mi * 16 + (lane >> 2);
            const int n = n0 + wn + ni * 8 + (lane & 3) * 2;
            const float b0 = __ldg(&bias[n]);
            const float b1 = __ldg(&bias[n + 1]);
            const float v00 = (acc[mi][ni][0] + b0) * scale;
            const float v01 = (acc[mi][ni][1] + b1) * scale;
            const float v10 = (acc[mi][ni][2] + b0) * scale;
            const float v11 = (acc[mi][ni][3] + b1) * scale;
            if (mode == 1) {
                const int h  = n >> 6;
                const int dk = n & (DK - 1);
#pragma unroll
                for (int rr = 0; rr < 2; rr++) {
                    const int mr = m + rr * 8;
                    const float p0 = rr ? v10 : v00;
                    const float p1 = rr ? v11 : v01;
                    const int bb = mr >> 11;
                    const int s  = mr & (S - 1);
                    __nv_bfloat16* base =
                        Ybz + (((size_t)bb * H + h) * S + s) * 128 + dk;
                    const uint32_t hp = cvt2bf(p1, p0);
                    const uint32_t lp = cvt2bf(p1 - bf_hi(hp), p0 - bf_lo(hp));
                    *(uint32_t*)(base)      = hp;
                    *(uint32_t*)(base + 64) = lp;
                }
            } else {
                *(float2*)(Yf + (size_t)m * D + n)       = make_float2(v00, v01);
                *(float2*)(Yf + (size_t)(m + 8) * D + n) = make_float2(v10, v11);
            }
        }
    }
}

// ---------------------------------------------------------------------------
// Tensor-core flash attention — round-10 shape (measured 775 us).
// ATK=32 key tiles, occupancy 2, 3-stage KV pipeline (stage 2 = recycled Q
// smem), fused bf16 hi/lo epilogue into the O-projection A buffer.
// ---------------------------------------------------------------------------
constexpr int ATQ = 128;
constexpr int ATK = 32;
constexpr int NKT = S / ATK;             // 64
constexpr int Q_SMEM = ATQ * 128 * 2;    // 32768
constexpr int KT_SMEM = ATK * 128 * 2;   // 8192
constexpr int AT_STAGE = 2 * KT_SMEM;    // 16384
constexpr int ATT_SMEM = Q_SMEM + 2 * AT_STAGE;  // 65536

__global__ __launch_bounds__(256, 2)
void attn_mma(const __nv_bfloat16* __restrict__ QKV, const int* __restrict__ mask,
              __nv_bfloat16* __restrict__ Aout)
{
    extern __shared__ char smem[];
    const uint32_t sq  = smem_u32(smem);
    const uint32_t skv = sq + Q_SMEM;
    const int tid = threadIdx.x, wid = tid >> 5, lane = tid & 31;
    const int b = blockIdx.z, h = blockIdx.y;
    const int q0blk = blockIdx.x * ATQ;
    const size_t headoff = ((size_t)(b * H + h) * S) * 128;
    const __nv_bfloat16* Qg = QKV + headoff + (size_t)q0blk * 128;
    const __nv_bfloat16* Kg = QKV + HEAD_SLOT + headoff;
    const __nv_bfloat16* Vg = QKV + 2 * HEAD_SLOT + headoff;
    const int wm = wid * 16;

    auto stage_of = [&](int c) -> uint32_t {
        const int s3 = c % 3;
        return (s3 == 0) ? skv : (s3 == 1) ? (skv + AT_STAGE) : sq;
    };

    auto load_kv = [&](int c) {
        const uint32_t st = stage_of(c);
        const int r = tid & 31, g = tid >> 5;
        const __nv_bfloat16* ks = Kg + (size_t)(c * ATK + r) * 128;
        const __nv_bfloat16* vs = Vg + (size_t)(c * ATK + r) * 128;
#pragma unroll
        for (int j = 0; j < 2; j++) {
            const int cg = g * 2 + j;
            const uint32_t so = (uint32_t)(((cg * 4 + (r >> 3)) * 8 + (r & 7)) * 16);
            cp16(st + so, ks + cg * 8);
            cp16(st + KT_SMEM + so, vs + cg * 8);
        }
        asm volatile("cp.async.commit_group;");
    };

    // Q tile load (grouped with stage-0 commit)
    {
        const int r = tid & 127, half = tid >> 7;
        const __nv_bfloat16* src = Qg + (size_t)r * 128;
#pragma unroll
        for (int j = 0; j < 8; j++) {
            const int cg = half * 8 + j;
            const uint32_t so = (uint32_t)(((cg * 16 + (r >> 3)) * 8 + (r & 7)) * 16);
            cp16(sq + so, src + cg * 8);
        }
    }
    load_kv(0);
    load_kv(1);

    asm volatile("cp.async.wait_group 1;" ::: "memory");
    __syncthreads();

    const int gA = lane >> 3, rA = lane & 7;

    // Q fragments -> registers (sq becomes KV stage 2 afterwards)
    uint32_t qhi[4][4], qlo[4][4];
#pragma unroll
    for (int kk = 0; kk < 4; kk++) {
        const int rg = (wm >> 3) + (gA & 1);
        const int cgh = 2 * kk + (gA >> 1);
        ldmatrix_x4(qhi[kk][0], qhi[kk][1], qhi[kk][2], qhi[kk][3],
                    sq + (uint32_t)(((cgh * 16 + rg) * 8 + rA) * 16));
        ldmatrix_x4(qlo[kk][0], qlo[kk][1], qlo[kk][2], qlo[kk][3],
                    sq + (uint32_t)((((cgh + 8) * 16 + rg) * 8 + rA) * 16));
    }
    __syncthreads();

    float o[8][4];
#pragma unroll
    for (int ng = 0; ng < 8; ng++)
#pragma unroll
        for (int r = 0; r < 4; r++) o[ng][r] = 0.f;
    float m0 = -1e30f, m1 = -1e30f, l0 = 0.f, l1 = 0.f;

    const int r0l = lane >> 2, c0l = (lane & 3) * 2;
    const int qg0 = q0blk + wm + r0l;
    const int* mr0 = mask + ((size_t)b * S + qg0) * S + c0l;
    const int* mr1 = mr0 + 8 * S;

#pragma unroll 1
    for (int c = 0; c < NKT; c++) {
        if (c + 1 < NKT) asm volatile("cp.async.wait_group 1;" ::: "memory");
        else             asm volatile("cp.async.wait_group 0;" ::: "memory");
        __syncthreads();
        if (c + 2 < NKT) load_kv(c + 2);

        const uint32_t kb_ = stage_of(c);
        const uint32_t vb_ = kb_ + KT_SMEM;

        // ---- scores: 32 keys -> sc[4][4] ----
        float sc[4][4];
#pragma unroll
        for (int ng = 0; ng < 4; ng++)
#pragma unroll
            for (int r = 0; r < 4; r++) sc[ng][r] = 0.f;

#pragma unroll
        for (int ng = 0; ng < 4; ng += 2) {
#pragma unroll
            for (int kk = 0; kk < 4; kk++) {
                uint32_t kh[4], kl[4];
                const int rg = ng + (gA >> 1);
                const int cg = 2 * kk + (gA & 1);
                ldmatrix_x4(kh[0], kh[1], kh[2], kh[3],
                            kb_ + (uint32_t)(((cg * 4 + rg) * 8 + rA) * 16));
                ldmatrix_x4(kl[0], kl[1], kl[2], kl[3],
                            kb_ + (uint32_t)((((cg + 8) * 4 + rg) * 8 + rA) * 16));
                mma_bf16(sc[ng],     qhi[kk], kh + 0);
                mma_bf16(sc[ng],     qhi[kk], kl + 0);
                mma_bf16(sc[ng],     qlo[kk], kh + 0);
                mma_bf16(sc[ng + 1], qhi[kk], kh + 2);
                mma_bf16(sc[ng + 1], qhi[kk], kl + 2);
                mma_bf16(sc[ng + 1], qlo[kk], kh + 2);
            }
        }

        // ---- mask ----
        const int koff = c * ATK;
#pragma unroll
        for (int ng = 0; ng < 4; ng++) {
            const int2 mA = *(const int2*)(mr0 + koff + ng * 8);
            const int2 mB = *(const int2*)(mr1 + koff + ng * 8);
            if (mA.x == 0) sc[ng][0] = -1e9f;
            if (mA.y == 0) sc[ng][1] = -1e9f;
            if (mB.x == 0) sc[ng][2] = -1e9f;
            if (mB.y == 0) sc[ng][3] = -1e9f;
        }

        // ---- online softmax ----
        float mx0 = sc[0][0], mx1 = sc[0][2];
#pragma unroll
        for (int ng = 0; ng < 4; ng++) {
            mx0 = fmaxf(mx0, fmaxf(sc[ng][0], sc[ng][1]));
            mx1 = fmaxf(mx1, fmaxf(sc[ng][2], sc[ng][3]));
        }
        mx0 = fmaxf(mx0, __shfl_xor_sync(0xffffffffu, mx0, 1));
        mx0 = fmaxf(mx0, __shfl_xor_sync(0xffffffffu, mx0, 2));
        mx1 = fmaxf(mx1, __shfl_xor_sync(0xffffffffu, mx1, 1));
        mx1 = fmaxf(mx1, __shfl_xor_sync(0xffffffffu, mx1, 2));

        const float mn0 = fmaxf(m0, mx0);
        const float mn1 = fmaxf(m1, mx1);
        const float cr0 = __expf(m0 - mn0);
        const float cr1 = __expf(m1 - mn1);
#pragma unroll
        for (int ng = 0; ng < 8; ng++) {
            o[ng][0] *= cr0; o[ng][1] *= cr0;
            o[ng][2] *= cr1; o[ng][3] *= cr1;
        }

        // ---- exp + P·V fused, kp-outer ----
        float rs0 = 0.f, rs1 = 0.f;
#pragma unroll
        for (int kp = 0; kp < 2; kp++) {
            const float p00 = __expf(sc[2*kp][0]   - mn0);
            const float p01 = __expf(sc[2*kp][1]   - mn0);
            const float p10 = __expf(sc[2*kp][2]   - mn1);
            const float p11 = __expf(sc[2*kp][3]   - mn1);
            const float p20 = __expf(sc[2*kp+1][0] - mn0);
            const float p21 = __expf(sc[2*kp+1][1] - mn0);
            const float p30 = __expf(sc[2*kp+1][2] - mn1);
            const float p31 = __expf(sc[2*kp+1][3] - mn1);
            rs0 += (p00 + p01) + (p20 + p21);
            rs1 += (p10 + p11) + (p30 + p31);
            uint32_t phi[4], plo[4];
            phi[0] = cvt2bf(p01, p00);
            phi[1] = cvt2bf(p11, p10);
            phi[2] = cvt2bf(p21, p20);
            phi[3] = cvt2bf(p31, p30);
            plo[0] = cvt2bf(p01 - bf_hi(phi[0]), p00 - bf_lo(phi[0]));
            plo[1] = cvt2bf(p11 - bf_hi(phi[1]), p10 - bf_lo(phi[1]));
            plo[2] = cvt2bf(p21 - bf_hi(phi[2]), p20 - bf_lo(phi[2]));
            plo[3] = cvt2bf(p31 - bf_hi(phi[3]), p30 - bf_lo(phi[3]));

            const int rg = 2 * kp + (gA & 1);
#pragma unroll
            for (int ng = 0; ng < 8; ng += 2) {
                const int cg = ng + (gA >> 1);
                uint32_t vh[4], vl[4];
                ldmatrix_x4_t(vh[0], vh[1], vh[2], vh[3],
                              vb_ + (uint32_t)(((cg * 4 + rg) * 8 + rA) * 16));
                ldmatrix_x4_t(vl[0], vl[1], vl[2], vl[3],
                              vb_ + (uint32_t)((((cg + 8) * 4 + rg) * 8 + rA) * 16));
                mma_bf16(o[ng],     phi, vh + 0);
                mma_bf16(o[ng],     phi, vl + 0);
                mma_bf16(o[ng],     plo, vh + 0);
                mma_bf16(o[ng + 1], phi, vh + 2);
                mma_bf16(o[ng + 1], phi, vl + 2);
                mma_bf16(o[ng + 1], plo, vh + 2);
            }
        }
        rs0 += __shfl_xor_sync(0xffffffffu, rs0, 1);
        rs0 += __shfl_xor_sync(0xffffffffu, rs0, 2);
        rs1 += __shfl_xor_sync(0xffffffffu, rs1, 1);
        rs1 += __shfl_xor_sync(0xffffffffu, rs1, 2);
        l0 = l0 * cr0 + rs0;
        l1 = l1 * cr1 + rs1;
        m0 = mn0; m1 = mn1;
    }

    // ---- epilogue: bf16 hi/lo straight into the O-proj A buffer ----
    const float inv0 = 1.f / l0;
    const float inv1 = 1.f / l1;
    __nv_bfloat16* dst0 = Aout + (size_t)(b * S + qg0) * KA + h * DK + c0l;
    __nv_bfloat16* dst1 = dst0 + (size_t)8 * KA;
#pragma unroll
    for (int ng = 0; ng < 8; ng++) {
        const float x0 = o[ng][0] * inv0, x1 = o[ng][1] * inv0;
        const float y0 = o[ng][2] * inv1, y1 = o[ng][3] * inv1;
        const uint32_t hx = cvt2bf(x1, x0);
        const uint32_t lx = cvt2bf(x1 - bf_hi(hx), x0 - bf_lo(hx));
        const uint32_t hy = cvt2bf(y1, y0);
        const uint32_t ly = cvt2bf(y1 - bf_hi(hy), y0 - bf_lo(hy));
        *(uint32_t*)(dst0 + ng * 8)     = hx;
        *(uint32_t*)(dst0 + D + ng * 8) = lx;
        *(uint32_t*)(dst1 + ng * 8)     = hy;
        *(uint32_t*)(dst1 + D + ng * 8) = ly;
    }
}

// ---------------------------------------------------------------------------
// launch
// ---------------------------------------------------------------------------
extern "C" void kernel_launch(void* const* d_in, const int* in_sizes, int n_in,
                              void* d_out, int out_size)
{
    const float* query = (const float*)d_in[0];
    const float* key_  = (const float*)d_in[1];
    const float* value = (const float*)d_in[2];
    const int*   amask = (const int*)  d_in[3];
    const float* w_q = (const float*)d_in[4];
    const float* b_q = (const float*)d_in[5];
    const float* w_k = (const float*)d_in[6];
    const float* b_k = (const float*)d_in[7];
    const float* w_v = (const float*)d_in[8];
    const float* b_v = (const float*)d_in[9];
    const float* w_o = (const float*)d_in[10];
    const float* b_o = (const float*)d_in[11];
    float* out = (float*)d_out;

    __nv_bfloat16 *gab3, *gwb4, *gqkvb;
    cudaGetSymbolAddress((void**)&gab3,  g_ab3);
    cudaGetSymbolAddress((void**)&gwb4,  g_wb4);
    cudaGetSymbolAddress((void**)&gqkvb, g_qkvb);

    cudaFuncSetAttribute(gemm_tc, cudaFuncAttributeMaxDynamicSharedMemorySize, GEMM_SMEM);
    cudaFuncSetAttribute(attn_mma, cudaFuncAttributeMaxDynamicSharedMemorySize, ATT_SMEM);

    conv_acts<<<dim3(M_TOTAL * D / (4 * 256), 3), 256>>>(query, key_, value, gab3);
    conv_ws  <<<dim3(D * D / (4 * 256), 4), 256>>>(w_q, w_k, w_v, w_o, gwb4);

    gemm_tc<<<dim3(D / 128, M_TOTAL / 128, 3), 256, GEMM_SMEM>>>(
        gab3, gwb4, b_q, b_k, b_v, nullptr, gqkvb, 1);

    attn_mma<<<dim3(S / ATQ, H, B), 256, ATT_SMEM>>>(gqkvb, amask, gab3);

    gemm_tc<<<dim3(D / 128, M_TOTAL / 128, 1), 256, GEMM_SMEM>>>(
        gab3, gwb4 + 3 * W_SLOT, b_o, b_o, b_o, out, nullptr, 0);
}

// round 14
// speedup vs baseline: 1.1707x; 1.0581x over previous
#include <cuda_runtime.h>
#include <cuda_bf16.h>
#include <cuda_fp16.h>
#include <cstdint>

// Problem constants
constexpr int B  = 4;
constexpr int S  = 2048;
constexpr int D  = 1024;
constexpr int H  = 16;
constexpr int DK = 64;
constexpr int M_TOTAL = B * S;   // 8192

constexpr int KA = 2 * D;        // 2048 (hi | lo)
constexpr size_t ACT_SLOT = (size_t)M_TOTAL * KA;
constexpr size_t W_SLOT   = (size_t)D * KA;
constexpr size_t Q_SLOT   = (size_t)B * H * S * 64;    // fp16 single
constexpr size_t KV_SLOT  = (size_t)B * H * S * 128;   // fp16 hi|lo

// ---------------------------------------------------------------------------
// Device scratch (allocation-free rule)
// ---------------------------------------------------------------------------
__device__ __nv_bfloat16 g_ab3[3 * ACT_SLOT];    // q,k,v acts; slot0 reused for attn out
__device__ __nv_bfloat16 g_wb4[4 * W_SLOT];      // w_q,w_k,w_v,w_o
__device__ __half g_qh[Q_SLOT];                  // Q head-major fp16 (pre-scaled)
__device__ __half g_kvh[2 * KV_SLOT];            // K, V head-major fp16 hi|lo

// ---------------------------------------------------------------------------
// helpers
// ---------------------------------------------------------------------------
__device__ __forceinline__ uint32_t smem_u32(const void* p) {
    uint32_t a;
    asm("{ .reg .u64 t; cvta.to.shared.u64 t, %1; cvt.u32.u64 %0, t; }"
        : "=r"(a) : "l"(p));
    return a;
}
__device__ __forceinline__ void cp16(uint32_t s, const void* g) {
    asm volatile("cp.async.cg.shared.global [%0], [%1], 16;" :: "r"(s), "l"(g));
}
__device__ __forceinline__ void ldmatrix_x4(uint32_t& r0, uint32_t& r1,
                                            uint32_t& r2, uint32_t& r3, uint32_t a) {
    asm volatile("ldmatrix.sync.aligned.m8n8.x4.shared.b16 {%0,%1,%2,%3}, [%4];"
                 : "=r"(r0), "=r"(r1), "=r"(r2), "=r"(r3) : "r"(a));
}
__device__ __forceinline__ void ldmatrix_x4_t(uint32_t& r0, uint32_t& r1,
                                              uint32_t& r2, uint32_t& r3, uint32_t a) {
    asm volatile("ldmatrix.sync.aligned.m8n8.x4.trans.shared.b16 {%0,%1,%2,%3}, [%4];"
                 : "=r"(r0), "=r"(r1), "=r"(r2), "=r"(r3) : "r"(a));
}
__device__ __forceinline__ void mma_bf16(float* c, const uint32_t* a, const uint32_t* b) {
    asm volatile("mma.sync.aligned.m16n8k16.row.col.f32.bf16.bf16.f32 "
                 "{%0,%1,%2,%3},{%4,%5,%6,%7},{%8,%9},{%0,%1,%2,%3};"
                 : "+f"(c[0]), "+f"(c[1]), "+f"(c[2]), "+f"(c[3])
                 : "r"(a[0]), "r"(a[1]), "r"(a[2]), "r"(a[3]), "r"(b[0]), "r"(b[1]));
}
__device__ __forceinline__ void mma_f16(float* c, const uint32_t* a, const uint32_t* b) {
    asm volatile("mma.sync.aligned.m16n8k16.row.col.f32.f16.f16.f32 "
                 "{%0,%1,%2,%3},{%4,%5,%6,%7},{%8,%9},{%0,%1,%2,%3};"
                 : "+f"(c[0]), "+f"(c[1]), "+f"(c[2]), "+f"(c[3])
                 : "r"(a[0]), "r"(a[1]), "r"(a[2]), "r"(a[3]), "r"(b[0]), "r"(b[1]));
}
__device__ __forceinline__ uint32_t cvt2bf(float phi, float plo) {
    uint32_t r;
    asm("cvt.rn.bf16x2.f32 %0, %1, %2;" : "=r"(r) : "f"(phi), "f"(plo));
    return r;
}
__device__ __forceinline__ uint32_t cvt2h(float phi, float plo) {
    uint32_t r;
    asm("cvt.rn.f16x2.f32 %0, %1, %2;" : "=r"(r) : "f"(phi), "f"(plo));
    return r;
}
__device__ __forceinline__ float bf_lo(uint32_t p) { return __uint_as_float(p << 16); }
__device__ __forceinline__ float bf_hi(uint32_t p) { return __uint_as_float(p & 0xFFFF0000u); }

// ---------------------------------------------------------------------------
// Conversion kernels: fp32 [R, D] -> bf16 hi/lo [R, 2D]
// ---------------------------------------------------------------------------
__device__ __forceinline__ void conv_body(const float* __restrict__ X,
                                          __nv_bfloat16* __restrict__ Yb)
{
    const int i = (blockIdx.x * 256 + threadIdx.x) * 4;
    float4 x = *(const float4*)(X + i);
    const int row = i >> 10;
    const int col = i & (D - 1);
    float xv[4] = {x.x, x.y, x.z, x.w};
    uint32_t hp[2], lp[2];
#pragma unroll
    for (int j = 0; j < 2; j++) {
        hp[j] = cvt2bf(xv[2*j+1], xv[2*j]);
        lp[j] = cvt2bf(xv[2*j+1] - bf_hi(hp[j]), xv[2*j] - bf_lo(hp[j]));
    }
    uint32_t* ph = (uint32_t*)(Yb + (size_t)row * KA + col);
    uint32_t* pl = (uint32_t*)(Yb + (size_t)row * KA + D + col);
    ph[0] = hp[0]; ph[1] = hp[1];
    pl[0] = lp[0]; pl[1] = lp[1];
}

__global__ __launch_bounds__(256)
void conv_acts(const float* __restrict__ q, const float* __restrict__ k,
               const float* __restrict__ v, __nv_bfloat16* __restrict__ Y3)
{
    const int z = blockIdx.y;
    const float* X = (z == 0) ? q : (z == 1) ? k : v;
    conv_body(X, Y3 + (size_t)z * ACT_SLOT);
}

__global__ __launch_bounds__(256)
void conv_ws(const float* __restrict__ wq, const float* __restrict__ wk,
             const float* __restrict__ wv, const float* __restrict__ wo,
             __nv_bfloat16* __restrict__ Y4)
{
    const int z = blockIdx.y;
    const float* X = (z == 0) ? wq : (z == 1) ? wk : (z == 2) ? wv : wo;
    conv_body(X, Y4 + (size_t)z * W_SLOT);
}

// ---------------------------------------------------------------------------
// bf16 mma.sync GEMM — round-6 shape (measured ~830 us for 4 GEMMs).
// mode 1 epilogue: z=0 -> Q as single fp16 (scaled 0.125) [B,H,S,64];
//                  z=1,2 -> K/V as fp16 hi/lo [B,H,S,128].
// mode 0: fp32 out.
// ---------------------------------------------------------------------------
constexpr int BKC = 32;
constexpr int NCH = D / BKC;               // 32 chunks
constexpr int TILE_B  = 128 * BKC * 2;     // 8192 B
constexpr int STAGE_B = 4 * TILE_B;        // 32 KB
constexpr int GEMM_SMEM = 3 * STAGE_B;     // 96 KB

__global__ __launch_bounds__(256)
void gemm_tc(const __nv_bfloat16* __restrict__ Ab, const __nv_bfloat16* __restrict__ Wb,
             const float* __restrict__ bq, const float* __restrict__ bk,
             const float* __restrict__ bv,
             float* __restrict__ Yf, __half* __restrict__ Yq,
             __half* __restrict__ Ykv, int mode)
{
    extern __shared__ char smem[];
    const uint32_t sbase = smem_u32(smem);
    const int tid  = threadIdx.x;
    const int wid  = tid >> 5;
    const int lane = tid & 31;
    const int z = blockIdx.z;
    const int m0 = blockIdx.y * 128;
    const int n0 = blockIdx.x * 128;
    const int wm = (wid >> 2) * 64;
    const int wn = (wid & 3) * 32;

    Ab += (size_t)z * ACT_SLOT;
    Wb += (size_t)z * W_SLOT;
    const float* bias = (z == 0) ? bq : (z == 1) ? bk : bv;
    const float scale = (mode == 1 && z == 0) ? 0.125f : 1.0f;

    float acc[4][4][4];
#pragma unroll
    for (int mi = 0; mi < 4; mi++)
#pragma unroll
        for (int ni = 0; ni < 4; ni++)
#pragma unroll
            for (int r = 0; r < 4; r++) acc[mi][ni][r] = 0.f;

    const int lr = tid >> 1;
    const int lh = tid & 1;

    auto load_chunk = [&](int c) {
        const uint32_t stage = sbase + (uint32_t)(c % 3) * STAGE_B;
        const int kc = c * BKC;
        const int mg = lr >> 3, r8 = lr & 7;
        const __nv_bfloat16* ga = Ab + (size_t)(m0 + lr) * KA + kc;
        const __nv_bfloat16* gw = Wb + (size_t)(n0 + lr) * KA + kc;
#pragma unroll
        for (int j = 0; j < 2; j++) {
            const int kg = lh * 2 + j;
            const uint32_t so = (uint32_t)((kg * 16 + mg) * 128 + r8 * 16);
            cp16(stage + 0 * TILE_B + so, ga + kg * 8);
            cp16(stage + 1 * TILE_B + so, ga + D + kg * 8);
            cp16(stage + 2 * TILE_B + so, gw + kg * 8);
            cp16(stage + 3 * TILE_B + so, gw + D + kg * 8);
        }
        asm volatile("cp.async.commit_group;");
    };

    load_chunk(0);
    load_chunk(1);

    const int gA = lane >> 3;
    const int rA = lane & 7;

    for (int c = 0; c < NCH; c++) {
        if (c + 1 < NCH) asm volatile("cp.async.wait_group 1;" ::: "memory");
        else             asm volatile("cp.async.wait_group 0;" ::: "memory");
        __syncthreads();
        if (c + 2 < NCH) load_chunk(c + 2);

        const uint32_t stage = sbase + (uint32_t)(c % 3) * STAGE_B;
        const uint32_t ahiB = stage;
        const uint32_t aloB = stage + TILE_B;
        const uint32_t whiB = stage + 2 * TILE_B;
        const uint32_t wloB = stage + 3 * TILE_B;

#pragma unroll
        for (int ks = 0; ks < 2; ks++) {
            const int kg0 = ks * 2;
            uint32_t ahi[4][4], alo[4][4], bhi[4][2], blo[4][2];
#pragma unroll
            for (int mi = 0; mi < 4; mi++) {
                const int mgB = (wm >> 3) + mi * 2 + (gA & 1);
                const int kgB = kg0 + (gA >> 1);
                const uint32_t off = (uint32_t)((kgB * 16 + mgB) * 128 + rA * 16);
                ldmatrix_x4(ahi[mi][0], ahi[mi][1], ahi[mi][2], ahi[mi][3], ahiB + off);
                ldmatrix_x4(alo[mi][0], alo[mi][1], alo[mi][2], alo[mi][3], aloB + off);
            }
#pragma unroll
            for (int np = 0; np < 2; np++) {
                const int ng  = (wn >> 3) + 2 * np + (gA >> 1);
                const int kgB = kg0 + (gA & 1);
                const uint32_t off = (uint32_t)((kgB * 16 + ng) * 128 + rA * 16);
                ldmatrix_x4(bhi[2*np][0], bhi[2*np][1], bhi[2*np+1][0], bhi[2*np+1][1],
                            whiB + off);
                ldmatrix_x4(blo[2*np][0], blo[2*np][1], blo[2*np+1][0], blo[2*np+1][1],
                            wloB + off);
            }
#pragma unroll
            for (int mi = 0; mi < 4; mi++)
#pragma unroll
                for (int ni = 0; ni < 4; ni++) {
                    mma_bf16(acc[mi][ni], ahi[mi], bhi[ni]);
                    mma_bf16(acc[mi][ni], ahi[mi], blo[ni]);
                    mma_bf16(acc[mi][ni], alo[mi], bhi[ni]);
                }
        }
    }

    // epilogue
#pragma unroll
    for (int mi = 0; mi < 4; mi++) {
#pragma unroll
        for (int ni = 0; ni < 4; ni++) {
            const int m = m0 + wm + mi * 16 + (lane >> 2);
            const int n = n0 + wn + ni * 8 + (lane & 3) * 2;
            const float b0 = __ldg(&bias[n]);
            const float b1 = __ldg(&bias[n + 1]);
            const float v00 = (acc[mi][ni][0] + b0) * scale;
            const float v01 = (acc[mi][ni][1] + b1) * scale;
            const float v10 = (acc[mi][ni][2] + b0) * scale;
            const float v11 = (acc[mi][ni][3] + b1) * scale;
            if (mode == 1) {
                const int h  = n >> 6;
                const int dk = n & (DK - 1);
#pragma unroll
                for (int rr = 0; rr < 2; rr++) {
                    const int mr = m + rr * 8;
                    const float p0 = rr ? v10 : v00;
                    const float p1 = rr ? v11 : v01;
                    const int bb = mr >> 11;
                    const int s  = mr & (S - 1);
                    const size_t rowi = ((size_t)bb * H + h) * S + s;
                    if (z == 0) {
                        *(__half2*)(Yq + rowi * 64 + dk) = __floats2half2_rn(p0, p1);
                    } else {
                        __half* base = Ykv + (size_t)(z - 1) * KV_SLOT + rowi * 128 + dk;
                        const __half h0 = __float2half_rn(p0);
                        const __half h1 = __float2half_rn(p1);
                        *(__half2*)(base) = __halves2half2(h0, h1);
                        *(__half2*)(base + 64) =
                            __floats2half2_rn(p0 - __half2float(h0), p1 - __half2float(h1));
                    }
                }
            } else {
                *(float2*)(Yf + (size_t)m * D + n)       = make_float2(v00, v01);
                *(float2*)(Yf + (size_t)(m + 8) * D + n) = make_float2(v10, v11);
            }
        }
    }
}

// ---------------------------------------------------------------------------
// Tensor-core flash attention — fp16 2-product:
//   scores = q_f16 · (k_hi + k_lo),  ctx = p_f16 · (v_hi + v_lo)
// 64 MMA/tile (was 96). Q smem 16KB == one KV stage (perfect 3-stage recycle).
// ATK=32 key tiles, occupancy 2, fused bf16 hi/lo epilogue into O-proj A buffer.
// ---------------------------------------------------------------------------
constexpr int ATQ = 128;
constexpr int ATK = 32;
constexpr int NKT = S / ATK;             // 64
constexpr int Q_SMEM = ATQ * 64 * 2;     // 16384
constexpr int KT_SMEM = ATK * 128 * 2;   // 8192
constexpr int AT_STAGE = 2 * KT_SMEM;    // 16384 == Q_SMEM
constexpr int ATT_SMEM = Q_SMEM + 2 * AT_STAGE;  // 49152

__global__ __launch_bounds__(256, 2)
void attn_mma(const __half* __restrict__ Qh, const __half* __restrict__ Kvh,
              const int* __restrict__ mask, __nv_bfloat16* __restrict__ Aout)
{
    extern __shared__ char smem[];
    const uint32_t sq  = smem_u32(smem);
    const uint32_t skv = sq + Q_SMEM;
    const int tid = threadIdx.x, wid = tid >> 5, lane = tid & 31;
    const int b = blockIdx.z, h = blockIdx.y;
    const int q0blk = blockIdx.x * ATQ;
    const size_t headrow = (size_t)(b * H + h) * S;
    const __half* Qg = Qh + (headrow + q0blk) * 64;
    const __half* Kg = Kvh + headrow * 128;
    const __half* Vg = Kvh + KV_SLOT + headrow * 128;
    const int wm = wid * 16;

    auto stage_of = [&](int c) -> uint32_t {
        const int s3 = c % 3;
        return (s3 == 0) ? skv : (s3 == 1) ? (skv + AT_STAGE) : sq;
    };

    auto load_kv = [&](int c) {
        const uint32_t st = stage_of(c);
        const int r = tid & 31, g = tid >> 5;
        const __half* ks = Kg + (size_t)(c * ATK + r) * 128;
        const __half* vs = Vg + (size_t)(c * ATK + r) * 128;
#pragma unroll
        for (int j = 0; j < 2; j++) {
            const int cg = g * 2 + j;
            const uint32_t so = (uint32_t)(((cg * 4 + (r >> 3)) * 8 + (r & 7)) * 16);
            cp16(st + so, ks + cg * 8);
            cp16(st + KT_SMEM + so, vs + cg * 8);
        }
        asm volatile("cp.async.commit_group;");
    };

    // Q tile load: 128 rows x 64 fp16 (8 quads/row), 4 quads/thread
    {
        const int r = tid & 127, half_ = tid >> 7;
        const __half* src = Qg + (size_t)r * 64;
#pragma unroll
        for (int j = 0; j < 4; j++) {
            const int cg = half_ * 4 + j;
            const uint32_t so = (uint32_t)(((cg * 16 + (r >> 3)) * 8 + (r & 7)) * 16);
            cp16(sq + so, src + cg * 8);
        }
    }
    load_kv(0);
    load_kv(1);

    asm volatile("cp.async.wait_group 1;" ::: "memory");
    __syncthreads();

    const int gA = lane >> 3, rA = lane & 7;

    // Q fragments -> registers (sq becomes KV stage 2 afterwards)
    uint32_t qh[4][4];
#pragma unroll
    for (int kk = 0; kk < 4; kk++) {
        const int rg = (wm >> 3) + (gA & 1);
        const int cgh = 2 * kk + (gA >> 1);
        ldmatrix_x4(qh[kk][0], qh[kk][1], qh[kk][2], qh[kk][3],
                    sq + (uint32_t)(((cgh * 16 + rg) * 8 + rA) * 16));
    }
    __syncthreads();

    float o[8][4];
#pragma unroll
    for (int ng = 0; ng < 8; ng++)
#pragma unroll
        for (int r = 0; r < 4; r++) o[ng][r] = 0.f;
    float m0 = -1e30f, m1 = -1e30f, l0 = 0.f, l1 = 0.f;

    const int r0l = lane >> 2, c0l = (lane & 3) * 2;
    const int qg0 = q0blk + wm + r0l;
    const int* mr0 = mask + ((size_t)b * S + qg0) * S + c0l;
    const int* mr1 = mr0 + 8 * S;

#pragma unroll 1
    for (int c = 0; c < NKT; c++) {
        if (c + 1 < NKT) asm volatile("cp.async.wait_group 1;" ::: "memory");
        else             asm volatile("cp.async.wait_group 0;" ::: "memory");
        __syncthreads();
        if (c + 2 < NKT) load_kv(c + 2);

        const uint32_t kb_ = stage_of(c);
        const uint32_t vb_ = kb_ + KT_SMEM;

        // ---- scores: q_f16 · (k_hi + k_lo) ----
        float sc[4][4];
#pragma unroll
        for (int ng = 0; ng < 4; ng++)
#pragma unroll
            for (int r = 0; r < 4; r++) sc[ng][r] = 0.f;

#pragma unroll
        for (int ng = 0; ng < 4; ng += 2) {
#pragma unroll
            for (int kk = 0; kk < 4; kk++) {
                uint32_t kh[4], kl[4];
                const int rg = ng + (gA >> 1);
                const int cg = 2 * kk + (gA & 1);
                ldmatrix_x4(kh[0], kh[1], kh[2], kh[3],
                            kb_ + (uint32_t)(((cg * 4 + rg) * 8 + rA) * 16));
                ldmatrix_x4(kl[0], kl[1], kl[2], kl[3],
                            kb_ + (uint32_t)((((cg + 8) * 4 + rg) * 8 + rA) * 16));
                mma_f16(sc[ng],     qh[kk], kh + 0);
                mma_f16(sc[ng],     qh[kk], kl + 0);
                mma_f16(sc[ng + 1], qh[kk], kh + 2);
                mma_f16(sc[ng + 1], qh[kk], kl + 2);
            }
        }

        // ---- mask ----
        const int koff = c * ATK;
#pragma unroll
        for (int ng = 0; ng < 4; ng++) {
            const int2 mA = *(const int2*)(mr0 + koff + ng * 8);
            const int2 mB = *(const int2*)(mr1 + koff + ng * 8);
            if (mA.x == 0) sc[ng][0] = -1e9f;
            if (mA.y == 0) sc[ng][1] = -1e9f;
            if (mB.x == 0) sc[ng][2] = -1e9f;
            if (mB.y == 0) sc[ng][3] = -1e9f;
        }

        // ---- online softmax ----
        float mx0 = sc[0][0], mx1 = sc[0][2];
#pragma unroll
        for (int ng = 0; ng < 4; ng++) {
            mx0 = fmaxf(mx0, fmaxf(sc[ng][0], sc[ng][1]));
            mx1 = fmaxf(mx1, fmaxf(sc[ng][2], sc[ng][3]));
        }
        mx0 = fmaxf(mx0, __shfl_xor_sync(0xffffffffu, mx0, 1));
        mx0 = fmaxf(mx0, __shfl_xor_sync(0xffffffffu, mx0, 2));
        mx1 = fmaxf(mx1, __shfl_xor_sync(0xffffffffu, mx1, 1));
        mx1 = fmaxf(mx1, __shfl_xor_sync(0xffffffffu, mx1, 2));

        const float mn0 = fmaxf(m0, mx0);
        const float mn1 = fmaxf(m1, mx1);
        const float cr0 = __expf(m0 - mn0);
        const float cr1 = __expf(m1 - mn1);
#pragma unroll
        for (int ng = 0; ng < 8; ng++) {
            o[ng][0] *= cr0; o[ng][1] *= cr0;
            o[ng][2] *= cr1; o[ng][3] *= cr1;
        }

        // ---- exp + P·V fused (P single fp16), kp-outer ----
        float rs0 = 0.f, rs1 = 0.f;
#pragma unroll
        for (int kp = 0; kp < 2; kp++) {
            const float p00 = __expf(sc[2*kp][0]   - mn0);
            const float p01 = __expf(sc[2*kp][1]   - mn0);
            const float p10 = __expf(sc[2*kp][2]   - mn1);
            const float p11 = __expf(sc[2*kp][3]   - mn1);
            const float p20 = __expf(sc[2*kp+1][0] - mn0);
            const float p21 = __expf(sc[2*kp+1][1] - mn0);
            const float p30 = __expf(sc[2*kp+1][2] - mn1);
            const float p31 = __expf(sc[2*kp+1][3] - mn1);
            rs0 += (p00 + p01) + (p20 + p21);
            rs1 += (p10 + p11) + (p30 + p31);
            uint32_t ph[4];
            ph[0] = cvt2h(p01, p00);
            ph[1] = cvt2h(p11, p10);
            ph[2] = cvt2h(p21, p20);
            ph[3] = cvt2h(p31, p30);

            const int rg = 2 * kp + (gA & 1);
#pragma unroll
            for (int ng = 0; ng < 8; ng += 2) {
                const int cg = ng + (gA >> 1);
                uint32_t vh[4], vl[4];
                ldmatrix_x4_t(vh[0], vh[1], vh[2], vh[3],
                              vb_ + (uint32_t)(((cg * 4 + rg) * 8 + rA) * 16));
                ldmatrix_x4_t(vl[0], vl[1], vl[2], vl[3],
                              vb_ + (uint32_t)((((cg + 8) * 4 + rg) * 8 + rA) * 16));
                mma_f16(o[ng],     ph, vh + 0);
                mma_f16(o[ng],     ph, vl + 0);
                mma_f16(o[ng + 1], ph, vh + 2);
                mma_f16(o[ng + 1], ph, vl + 2);
            }
        }
        rs0 += __shfl_xor_sync(0xffffffffu, rs0, 1);
        rs0 += __shfl_xor_sync(0xffffffffu, rs0, 2);
        rs1 += __shfl_xor_sync(0xffffffffu, rs1, 1);
        rs1 += __shfl_xor_sync(0xffffffffu, rs1, 2);
        l0 = l0 * cr0 + rs0;
        l1 = l1 * cr1 + rs1;
        m0 = mn0; m1 = mn1;
    }

    // ---- epilogue: bf16 hi/lo straight into the O-proj A buffer ----
    const float inv0 = 1.f / l0;
    const float inv1 = 1.f / l1;
    __nv_bfloat16* dst0 = Aout + (size_t)(b * S + qg0) * KA + h * DK + c0l;
    __nv_bfloat16* dst1 = dst0 + (size_t)8 * KA;
#pragma unroll
    for (int ng = 0; ng < 8; ng++) {
        const float x0 = o[ng][0] * inv0, x1 = o[ng][1] * inv0;
        const float y0 = o[ng][2] * inv1, y1 = o[ng][3] * inv1;
        const uint32_t hx = cvt2bf(x1, x0);
        const uint32_t lx = cvt2bf(x1 - bf_hi(hx), x0 - bf_lo(hx));
        const uint32_t hy = cvt2bf(y1, y0);
        const uint32_t ly = cvt2bf(y1 - bf_hi(hy), y0 - bf_lo(hy));
        *(uint32_t*)(dst0 + ng * 8)     = hx;
        *(uint32_t*)(dst0 + D + ng * 8) = lx;
        *(uint32_t*)(dst1 + ng * 8)     = hy;
        *(uint32_t*)(dst1 + D + ng * 8) = ly;
    }
}

// ---------------------------------------------------------------------------
// launch
// ---------------------------------------------------------------------------
extern "C" void kernel_launch(void* const* d_in, const int* in_sizes, int n_in,
                              void* d_out, int out_size)
{
    const float* query = (const float*)d_in[0];
    const float* key_  = (const float*)d_in[1];
    const float* value = (const float*)d_in[2];
    const int*   amask = (const int*)  d_in[3];
    const float* w_q = (const float*)d_in[4];
    const float* b_q = (const float*)d_in[5];
    const float* w_k = (const float*)d_in[6];
    const float* b_k = (const float*)d_in[7];
    const float* w_v = (const float*)d_in[8];
    const float* b_v = (const float*)d_in[9];
    const float* w_o = (const float*)d_in[10];
    const float* b_o = (const float*)d_in[11];
    float* out = (float*)d_out;

    __nv_bfloat16 *gab3, *gwb4;
    __half *gqh, *gkvh;
    cudaGetSymbolAddress((void**)&gab3, g_ab3);
    cudaGetSymbolAddress((void**)&gwb4, g_wb4);
    cudaGetSymbolAddress((void**)&gqh,  g_qh);
    cudaGetSymbolAddress((void**)&gkvh, g_kvh);

    cudaFuncSetAttribute(gemm_tc, cudaFuncAttributeMaxDynamicSharedMemorySize, GEMM_SMEM);
    cudaFuncSetAttribute(attn_mma, cudaFuncAttributeMaxDynamicSharedMemorySize, ATT_SMEM);

    conv_acts<<<dim3(M_TOTAL * D / (4 * 256), 3), 256>>>(query, key_, value, gab3);
    conv_ws  <<<dim3(D * D / (4 * 256), 4), 256>>>(w_q, w_k, w_v, w_o, gwb4);

    gemm_tc<<<dim3(D / 128, M_TOTAL / 128, 3), 256, GEMM_SMEM>>>(
        gab3, gwb4, b_q, b_k, b_v, nullptr, gqh, gkvh, 1);

    attn_mma<<<dim3(S / ATQ, H, B), 256, ATT_SMEM>>>(gqh, gkvh, amask, gab3);

    gemm_tc<<<dim3(D / 128, M_TOTAL / 128, 1), 256, GEMM_SMEM>>>(
        gab3, gwb4 + 3 * W_SLOT, b_o, b_o, b_o, out, nullptr, nullptr, 0);
}

// round 15
// speedup vs baseline: 1.3900x; 1.1874x over previous
#include <cuda_runtime.h>
#include <cuda_bf16.h>
#include <cuda_fp16.h>
#include <cstdint>

// Problem constants
constexpr int B  = 4;
constexpr int S  = 2048;
constexpr int D  = 1024;
constexpr int H  = 16;
constexpr int DK = 64;
constexpr int M_TOTAL = B * S;   // 8192

constexpr int KA = 2 * D;        // 2048 (w_hi | w_lo)
constexpr size_t ACT_SLOT = (size_t)M_TOTAL * D;       // fp16 single
constexpr size_t W_SLOT   = (size_t)D * KA;            // fp16 hi|lo
constexpr size_t Q_SLOT   = (size_t)B * H * S * 64;    // fp16 single
constexpr size_t KV_SLOT  = (size_t)B * H * S * 128;   // fp16 hi|lo

// ---------------------------------------------------------------------------
// Device scratch (allocation-free rule)
// ---------------------------------------------------------------------------
__device__ __half g_ah3[3 * ACT_SLOT];   // q,k,v acts fp16; slot0 reused for attn ctx
__device__ __half g_wh4[4 * W_SLOT];     // w_q,w_k,w_v,w_o fp16 hi/lo
__device__ __half g_qh[Q_SLOT];          // Q head-major fp16 (pre-scaled)
__device__ __half g_kvh[2 * KV_SLOT];    // K, V head-major fp16 hi|lo

// ---------------------------------------------------------------------------
// helpers
// ---------------------------------------------------------------------------
__device__ __forceinline__ uint32_t smem_u32(const void* p) {
    uint32_t a;
    asm("{ .reg .u64 t; cvta.to.shared.u64 t, %1; cvt.u32.u64 %0, t; }"
        : "=r"(a) : "l"(p));
    return a;
}
__device__ __forceinline__ void cp16(uint32_t s, const void* g) {
    asm volatile("cp.async.cg.shared.global [%0], [%1], 16;" :: "r"(s), "l"(g));
}
__device__ __forceinline__ void ldmatrix_x4(uint32_t& r0, uint32_t& r1,
                                            uint32_t& r2, uint32_t& r3, uint32_t a) {
    asm volatile("ldmatrix.sync.aligned.m8n8.x4.shared.b16 {%0,%1,%2,%3}, [%4];"
                 : "=r"(r0), "=r"(r1), "=r"(r2), "=r"(r3) : "r"(a));
}
__device__ __forceinline__ void ldmatrix_x4_t(uint32_t& r0, uint32_t& r1,
                                              uint32_t& r2, uint32_t& r3, uint32_t a) {
    asm volatile("ldmatrix.sync.aligned.m8n8.x4.trans.shared.b16 {%0,%1,%2,%3}, [%4];"
                 : "=r"(r0), "=r"(r1), "=r"(r2), "=r"(r3) : "r"(a));
}
__device__ __forceinline__ void mma_f16(float* c, const uint32_t* a, const uint32_t* b) {
    asm volatile("mma.sync.aligned.m16n8k16.row.col.f32.f16.f16.f32 "
                 "{%0,%1,%2,%3},{%4,%5,%6,%7},{%8,%9},{%0,%1,%2,%3};"
                 : "+f"(c[0]), "+f"(c[1]), "+f"(c[2]), "+f"(c[3])
                 : "r"(a[0]), "r"(a[1]), "r"(a[2]), "r"(a[3]), "r"(b[0]), "r"(b[1]));
}
__device__ __forceinline__ uint32_t cvt2h(float phi, float plo) {
    uint32_t r;
    asm("cvt.rn.f16x2.f32 %0, %1, %2;" : "=r"(r) : "f"(phi), "f"(plo));
    return r;
}

// ---------------------------------------------------------------------------
// Conversion kernels
// ---------------------------------------------------------------------------
// activations: fp32 [R, D] -> fp16 single [R, D]
__global__ __launch_bounds__(256)
void conv_acts(const float* __restrict__ q, const float* __restrict__ k,
               const float* __restrict__ v, __half* __restrict__ Y3)
{
    const int z = blockIdx.y;
    const float* X = (z == 0) ? q : (z == 1) ? k : v;
    __half* Yb = Y3 + (size_t)z * ACT_SLOT;
    const int i = (blockIdx.x * 256 + threadIdx.x) * 4;
    float4 x = *(const float4*)(X + i);
    uint32_t* o = (uint32_t*)(Yb + i);
    o[0] = cvt2h(x.y, x.x);
    o[1] = cvt2h(x.w, x.z);
}

// weights: fp32 [N, D] -> fp16 hi/lo [N, 2D]
__global__ __launch_bounds__(256)
void conv_ws(const float* __restrict__ wq, const float* __restrict__ wk,
             const float* __restrict__ wv, const float* __restrict__ wo,
             __half* __restrict__ Y4)
{
    const int z = blockIdx.y;
    const float* X = (z == 0) ? wq : (z == 1) ? wk : (z == 2) ? wv : wo;
    __half* Yb = Y4 + (size_t)z * W_SLOT;
    const int i = (blockIdx.x * 256 + threadIdx.x) * 4;
    float4 x = *(const float4*)(X + i);
    const int row = i >> 10;
    const int col = i & (D - 1);
    float xv[4] = {x.x, x.y, x.z, x.w};
    __half h[4];
    float  r[4];
#pragma unroll
    for (int j = 0; j < 4; j++) {
        h[j] = __float2half_rn(xv[j]);
        r[j] = xv[j] - __half2float(h[j]);
    }
    __half* ph = Yb + (size_t)row * KA + col;
    __half* pl = ph + D;
    *(__half2*)(ph)     = __halves2half2(h[0], h[1]);
    *(__half2*)(ph + 2) = __halves2half2(h[2], h[3]);
    *(uint32_t*)(pl)     = cvt2h(r[1], r[0]);
    *(uint32_t*)(pl + 2) = cvt2h(r[3], r[2]);
}

// ---------------------------------------------------------------------------
// fp16 mma.sync GEMM, 2-product: Y = a_f16 · (w_hi + w_lo) + bias
// 128x128 CTA, 256 threads / 8 warps, warp tile 64x32, 3-stage pipeline.
// Stage = A(8K) + Whi(8K) + Wlo(8K) = 24 KB; natural footprint fits occ 2.
// ---------------------------------------------------------------------------
constexpr int BKC = 32;
constexpr int NCH = D / BKC;               // 32 chunks
constexpr int TILE_B  = 128 * BKC * 2;     // 8192 B
constexpr int STAGE_B = 3 * TILE_B;        // 24 KB
constexpr int GEMM_SMEM = 3 * STAGE_B;     // 72 KB

__global__ __launch_bounds__(256, 2)
void gemm_tc(const __half* __restrict__ Ab, const __half* __restrict__ Wb,
             const float* __restrict__ bq, const float* __restrict__ bk,
             const float* __restrict__ bv,
             float* __restrict__ Yf, __half* __restrict__ Yq,
             __half* __restrict__ Ykv, int mode)
{
    extern __shared__ char smem[];
    const uint32_t sbase = smem_u32(smem);
    const int tid  = threadIdx.x;
    const int wid  = tid >> 5;
    const int lane = tid & 31;
    const int z = blockIdx.z;
    const int m0 = blockIdx.y * 128;
    const int n0 = blockIdx.x * 128;
    const int wm = (wid >> 2) * 64;
    const int wn = (wid & 3) * 32;

    Ab += (size_t)z * ACT_SLOT;
    Wb += (size_t)z * W_SLOT;
    const float* bias = (z == 0) ? bq : (z == 1) ? bk : bv;
    const float scale = (mode == 1 && z == 0) ? 0.125f : 1.0f;

    float acc[4][4][4];
#pragma unroll
    for (int mi = 0; mi < 4; mi++)
#pragma unroll
        for (int ni = 0; ni < 4; ni++)
#pragma unroll
            for (int r = 0; r < 4; r++) acc[mi][ni][r] = 0.f;

    const int lr = tid >> 1;
    const int lh = tid & 1;

    auto load_chunk = [&](int c) {
        const uint32_t stage = sbase + (uint32_t)(c % 3) * STAGE_B;
        const int kc = c * BKC;
        const int mg = lr >> 3, r8 = lr & 7;
        const __half* ga = Ab + (size_t)(m0 + lr) * D + kc;
        const __half* gw = Wb + (size_t)(n0 + lr) * KA + kc;
#pragma unroll
        for (int j = 0; j < 2; j++) {
            const int kg = lh * 2 + j;
            const uint32_t so = (uint32_t)((kg * 16 + mg) * 128 + r8 * 16);
            cp16(stage + 0 * TILE_B + so, ga + kg * 8);          // A
            cp16(stage + 1 * TILE_B + so, gw + kg * 8);          // W hi
            cp16(stage + 2 * TILE_B + so, gw + D + kg * 8);      // W lo
        }
        asm volatile("cp.async.commit_group;");
    };

    load_chunk(0);
    load_chunk(1);

    const int gA = lane >> 3;
    const int rA = lane & 7;

    for (int c = 0; c < NCH; c++) {
        if (c + 1 < NCH) asm volatile("cp.async.wait_group 1;" ::: "memory");
        else             asm volatile("cp.async.wait_group 0;" ::: "memory");
        __syncthreads();
        if (c + 2 < NCH) load_chunk(c + 2);

        const uint32_t stage = sbase + (uint32_t)(c % 3) * STAGE_B;
        const uint32_t aB   = stage;
        const uint32_t whiB = stage + TILE_B;
        const uint32_t wloB = stage + 2 * TILE_B;

#pragma unroll
        for (int ks = 0; ks < 2; ks++) {
            const int kg0 = ks * 2;
            uint32_t af[4][4], bhi[4][2], blo[4][2];
#pragma unroll
            for (int mi = 0; mi < 4; mi++) {
                const int mgB = (wm >> 3) + mi * 2 + (gA & 1);
                const int kgB = kg0 + (gA >> 1);
                const uint32_t off = (uint32_t)((kgB * 16 + mgB) * 128 + rA * 16);
                ldmatrix_x4(af[mi][0], af[mi][1], af[mi][2], af[mi][3], aB + off);
            }
#pragma unroll
            for (int np = 0; np < 2; np++) {
                const int ng  = (wn >> 3) + 2 * np + (gA >> 1);
                const int kgB = kg0 + (gA & 1);
                const uint32_t off = (uint32_t)((kgB * 16 + ng) * 128 + rA * 16);
                ldmatrix_x4(bhi[2*np][0], bhi[2*np][1], bhi[2*np+1][0], bhi[2*np+1][1],
                            whiB + off);
                ldmatrix_x4(blo[2*np][0], blo[2*np][1], blo[2*np+1][0], blo[2*np+1][1],
                            wloB + off);
            }
#pragma unroll
            for (int mi = 0; mi < 4; mi++)
#pragma unroll
                for (int ni = 0; ni < 4; ni++) {
                    mma_f16(acc[mi][ni], af[mi], bhi[ni]);
                    mma_f16(acc[mi][ni], af[mi], blo[ni]);
                }
        }
    }

    // epilogue
#pragma unroll
    for (int mi = 0; mi < 4; mi++) {
#pragma unroll
        for (int ni = 0; ni < 4; ni++) {
            const int m = m0 + wm + mi * 16 + (lane >> 2);
            const int n = n0 + wn + ni * 8 + (lane & 3) * 2;
            const float b0 = __ldg(&bias[n]);
            const float b1 = __ldg(&bias[n + 1]);
            const float v00 = (acc[mi][ni][0] + b0) * scale;
            const float v01 = (acc[mi][ni][1] + b1) * scale;
            const float v10 = (acc[mi][ni][2] + b0) * scale;
            const float v11 = (acc[mi][ni][3] + b1) * scale;
            if (mode == 1) {
                const int h  = n >> 6;
                const int dk = n & (DK - 1);
#pragma unroll
                for (int rr = 0; rr < 2; rr++) {
                    const int mr = m + rr * 8;
                    const float p0 = rr ? v10 : v00;
                    const float p1 = rr ? v11 : v01;
                    const int bb = mr >> 11;
                    const int s  = mr & (S - 1);
                    const size_t rowi = ((size_t)bb * H + h) * S + s;
                    if (z == 0) {
                        *(__half2*)(Yq + rowi * 64 + dk) = __floats2half2_rn(p0, p1);
                    } else {
                        __half* base = Ykv + (size_t)(z - 1) * KV_SLOT + rowi * 128 + dk;
                        const __half h0 = __float2half_rn(p0);
                        const __half h1 = __float2half_rn(p1);
                        *(__half2*)(base) = __halves2half2(h0, h1);
                        *(__half2*)(base + 64) =
                            __floats2half2_rn(p0 - __half2float(h0), p1 - __half2float(h1));
                    }
                }
            } else {
                *(float2*)(Yf + (size_t)m * D + n)       = make_float2(v00, v01);
                *(float2*)(Yf + (size_t)(m + 8) * D + n) = make_float2(v10, v11);
            }
        }
    }
}

// ---------------------------------------------------------------------------
// Tensor-core flash attention — fp16 2-product (round-14 shape, 693 us).
// Epilogue now writes ctx as fp16 single into the O-proj A buffer.
// ---------------------------------------------------------------------------
constexpr int ATQ = 128;
constexpr int ATK = 32;
constexpr int NKT = S / ATK;             // 64
constexpr int Q_SMEM = ATQ * 64 * 2;     // 16384
constexpr int KT_SMEM = ATK * 128 * 2;   // 8192
constexpr int AT_STAGE = 2 * KT_SMEM;    // 16384 == Q_SMEM
constexpr int ATT_SMEM = Q_SMEM + 2 * AT_STAGE;  // 49152

__global__ __launch_bounds__(256, 2)
void attn_mma(const __half* __restrict__ Qh, const __half* __restrict__ Kvh,
              const int* __restrict__ mask, __half* __restrict__ Aout)
{
    extern __shared__ char smem[];
    const uint32_t sq  = smem_u32(smem);
    const uint32_t skv = sq + Q_SMEM;
    const int tid = threadIdx.x, wid = tid >> 5, lane = tid & 31;
    const int b = blockIdx.z, h = blockIdx.y;
    const int q0blk = blockIdx.x * ATQ;
    const size_t headrow = (size_t)(b * H + h) * S;
    const __half* Qg = Qh + (headrow + q0blk) * 64;
    const __half* Kg = Kvh + headrow * 128;
    const __half* Vg = Kvh + KV_SLOT + headrow * 128;
    const int wm = wid * 16;

    auto stage_of = [&](int c) -> uint32_t {
        const int s3 = c % 3;
        return (s3 == 0) ? skv : (s3 == 1) ? (skv + AT_STAGE) : sq;
    };

    auto load_kv = [&](int c) {
        const uint32_t st = stage_of(c);
        const int r = tid & 31, g = tid >> 5;
        const __half* ks = Kg + (size_t)(c * ATK + r) * 128;
        const __half* vs = Vg + (size_t)(c * ATK + r) * 128;
#pragma unroll
        for (int j = 0; j < 2; j++) {
            const int cg = g * 2 + j;
            const uint32_t so = (uint32_t)(((cg * 4 + (r >> 3)) * 8 + (r & 7)) * 16);
            cp16(st + so, ks + cg * 8);
            cp16(st + KT_SMEM + so, vs + cg * 8);
        }
        asm volatile("cp.async.commit_group;");
    };

    // Q tile load
    {
        const int r = tid & 127, half_ = tid >> 7;
        const __half* src = Qg + (size_t)r * 64;
#pragma unroll
        for (int j = 0; j < 4; j++) {
            const int cg = half_ * 4 + j;
            const uint32_t so = (uint32_t)(((cg * 16 + (r >> 3)) * 8 + (r & 7)) * 16);
            cp16(sq + so, src + cg * 8);
        }
    }
    load_kv(0);
    load_kv(1);

    asm volatile("cp.async.wait_group 1;" ::: "memory");
    __syncthreads();

    const int gA = lane >> 3, rA = lane & 7;

    // Q fragments -> registers (sq becomes KV stage 2 afterwards)
    uint32_t qh[4][4];
#pragma unroll
    for (int kk = 0; kk < 4; kk++) {
        const int rg = (wm >> 3) + (gA & 1);
        const int cgh = 2 * kk + (gA >> 1);
        ldmatrix_x4(qh[kk][0], qh[kk][1], qh[kk][2], qh[kk][3],
                    sq + (uint32_t)(((cgh * 16 + rg) * 8 + rA) * 16));
    }
    __syncthreads();

    float o[8][4];
#pragma unroll
    for (int ng = 0; ng < 8; ng++)
#pragma unroll
        for (int r = 0; r < 4; r++) o[ng][r] = 0.f;
    float m0 = -1e30f, m1 = -1e30f, l0 = 0.f, l1 = 0.f;

    const int r0l = lane >> 2, c0l = (lane & 3) * 2;
    const int qg0 = q0blk + wm + r0l;
    const int* mr0 = mask + ((size_t)b * S + qg0) * S + c0l;
    const int* mr1 = mr0 + 8 * S;

#pragma unroll 1
    for (int c = 0; c < NKT; c++) {
        if (c + 1 < NKT) asm volatile("cp.async.wait_group 1;" ::: "memory");
        else             asm volatile("cp.async.wait_group 0;" ::: "memory");
        __syncthreads();
        if (c + 2 < NKT) load_kv(c + 2);

        const uint32_t kb_ = stage_of(c);
        const uint32_t vb_ = kb_ + KT_SMEM;

        // ---- scores: q_f16 · (k_hi + k_lo) ----
        float sc[4][4];
#pragma unroll
        for (int ng = 0; ng < 4; ng++)
#pragma unroll
            for (int r = 0; r < 4; r++) sc[ng][r] = 0.f;

#pragma unroll
        for (int ng = 0; ng < 4; ng += 2) {
#pragma unroll
            for (int kk = 0; kk < 4; kk++) {
                uint32_t kh[4], kl[4];
                const int rg = ng + (gA >> 1);
                const int cg = 2 * kk + (gA & 1);
                ldmatrix_x4(kh[0], kh[1], kh[2], kh[3],
                            kb_ + (uint32_t)(((cg * 4 + rg) * 8 + rA) * 16));
                ldmatrix_x4(kl[0], kl[1], kl[2], kl[3],
                            kb_ + (uint32_t)((((cg + 8) * 4 + rg) * 8 + rA) * 16));
                mma_f16(sc[ng],     qh[kk], kh + 0);
                mma_f16(sc[ng],     qh[kk], kl + 0);
                mma_f16(sc[ng + 1], qh[kk], kh + 2);
                mma_f16(sc[ng + 1], qh[kk], kl + 2);
            }
        }

        // ---- mask ----
        const int koff = c * ATK;
#pragma unroll
        for (int ng = 0; ng < 4; ng++) {
            const int2 mA = *(const int2*)(mr0 + koff + ng * 8);
            const int2 mB = *(const int2*)(mr1 + koff + ng * 8);
            if (mA.x == 0) sc[ng][0] = -1e9f;
            if (mA.y == 0) sc[ng][1] = -1e9f;
            if (mB.x == 0) sc[ng][2] = -1e9f;
            if (mB.y == 0) sc[ng][3] = -1e9f;
        }

        // ---- online softmax ----
        float mx0 = sc[0][0], mx1 = sc[0][2];
#pragma unroll
        for (int ng = 0; ng < 4; ng++) {
            mx0 = fmaxf(mx0, fmaxf(sc[ng][0], sc[ng][1]));
            mx1 = fmaxf(mx1, fmaxf(sc[ng][2], sc[ng][3]));
        }
        mx0 = fmaxf(mx0, __shfl_xor_sync(0xffffffffu, mx0, 1));
        mx0 = fmaxf(mx0, __shfl_xor_sync(0xffffffffu, mx0, 2));
        mx1 = fmaxf(mx1, __shfl_xor_sync(0xffffffffu, mx1, 1));
        mx1 = fmaxf(mx1, __shfl_xor_sync(0xffffffffu, mx1, 2));

        const float mn0 = fmaxf(m0, mx0);
        const float mn1 = fmaxf(m1, mx1);
        const float cr0 = __expf(m0 - mn0);
        const float cr1 = __expf(m1 - mn1);
#pragma unroll
        for (int ng = 0; ng < 8; ng++) {
            o[ng][0] *= cr0; o[ng][1] *= cr0;
            o[ng][2] *= cr1; o[ng][3] *= cr1;
        }

        // ---- exp + P·V fused (P single fp16), kp-outer ----
        float rs0 = 0.f, rs1 = 0.f;
#pragma unroll
        for (int kp = 0; kp < 2; kp++) {
            const float p00 = __expf(sc[2*kp][0]   - mn0);
            const float p01 = __expf(sc[2*kp][1]   - mn0);
            const float p10 = __expf(sc[2*kp][2]   - mn1);
            const float p11 = __expf(sc[2*kp][3]   - mn1);
            const float p20 = __expf(sc[2*kp+1][0] - mn0);
            const float p21 = __expf(sc[2*kp+1][1] - mn0);
            const float p30 = __expf(sc[2*kp+1][2] - mn1);
            const float p31 = __expf(sc[2*kp+1][3] - mn1);
            rs0 += (p00 + p01) + (p20 + p21);
            rs1 += (p10 + p11) + (p30 + p31);
            uint32_t ph[4];
            ph[0] = cvt2h(p01, p00);
            ph[1] = cvt2h(p11, p10);
            ph[2] = cvt2h(p21, p20);
            ph[3] = cvt2h(p31, p30);

            const int rg = 2 * kp + (gA & 1);
#pragma unroll
            for (int ng = 0; ng < 8; ng += 2) {
                const int cg = ng + (gA >> 1);
                uint32_t vh[4], vl[4];
                ldmatrix_x4_t(vh[0], vh[1], vh[2], vh[3],
                              vb_ + (uint32_t)(((cg * 4 + rg) * 8 + rA) * 16));
                ldmatrix_x4_t(vl[0], vl[1], vl[2], vl[3],
                              vb_ + (uint32_t)((((cg + 8) * 4 + rg) * 8 + rA) * 16));
                mma_f16(o[ng],     ph, vh + 0);
                mma_f16(o[ng],     ph, vl + 0);
                mma_f16(o[ng + 1], ph, vh + 2);
                mma_f16(o[ng + 1], ph, vl + 2);
            }
        }
        rs0 += __shfl_xor_sync(0xffffffffu, rs0, 1);
        rs0 += __shfl_xor_sync(0xffffffffu, rs0, 2);
        rs1 += __shfl_xor_sync(0xffffffffu, rs1, 1);
        rs1 += __shfl_xor_sync(0xffffffffu, rs1, 2);
        l0 = l0 * cr0 + rs0;
        l1 = l1 * cr1 + rs1;
        m0 = mn0; m1 = mn1;
    }

    // ---- epilogue: ctx fp16 single into the O-proj A buffer ----
    const float inv0 = 1.f / l0;
    const float inv1 = 1.f / l1;
    __half* dst0 = Aout + (size_t)(b * S + qg0) * D + h * DK + c0l;
    __half* dst1 = dst0 + (size_t)8 * D;
#pragma unroll
    for (int ng = 0; ng < 8; ng++) {
        *(uint32_t*)(dst0 + ng * 8) = cvt2h(o[ng][1] * inv0, o[ng][0] * inv0);
        *(uint32_t*)(dst1 + ng * 8) = cvt2h(o[ng][3] * inv1, o[ng][2] * inv1);
    }
}

// ---------------------------------------------------------------------------
// launch
// ---------------------------------------------------------------------------
extern "C" void kernel_launch(void* const* d_in, const int* in_sizes, int n_in,
                              void* d_out, int out_size)
{
    const float* query = (const float*)d_in[0];
    const float* key_  = (const float*)d_in[1];
    const float* value = (const float*)d_in[2];
    const int*   amask = (const int*)  d_in[3];
    const float* w_q = (const float*)d_in[4];
    const float* b_q = (const float*)d_in[5];
    const float* w_k = (const float*)d_in[6];
    const float* b_k = (const float*)d_in[7];
    const float* w_v = (const float*)d_in[8];
    const float* b_v = (const float*)d_in[9];
    const float* w_o = (const float*)d_in[10];
    const float* b_o = (const float*)d_in[11];
    float* out = (float*)d_out;

    __half *gah3, *gwh4, *gqh, *gkvh;
    cudaGetSymbolAddress((void**)&gah3, g_ah3);
    cudaGetSymbolAddress((void**)&gwh4, g_wh4);
    cudaGetSymbolAddress((void**)&gqh,  g_qh);
    cudaGetSymbolAddress((void**)&gkvh, g_kvh);

    cudaFuncSetAttribute(gemm_tc, cudaFuncAttributeMaxDynamicSharedMemorySize, GEMM_SMEM);
    cudaFuncSetAttribute(attn_mma, cudaFuncAttributeMaxDynamicSharedMemorySize, ATT_SMEM);

    conv_acts<<<dim3(M_TOTAL * D / (4 * 256), 3), 256>>>(query, key_, value, gah3);
    conv_ws  <<<dim3(D * D / (4 * 256), 4), 256>>>(w_q, w_k, w_v, w_o, gwh4);

    gemm_tc<<<dim3(D / 128, M_TOTAL / 128, 3), 256, GEMM_SMEM>>>(
        gah3, gwh4, b_q, b_k, b_v, nullptr, gqh, gkvh, 1);

    attn_mma<<<dim3(S / ATQ, H, B), 256, ATT_SMEM>>>(gqh, gkvh, amask, gah3);

    gemm_tc<<<dim3(D / 128, M_TOTAL / 128, 1), 256, GEMM_SMEM>>>(
        gah3, gwh4 + 3 * W_SLOT, b_o, b_o, b_o, out, nullptr, nullptr, 0);
}

// round 16
// speedup vs baseline: 1.7358x; 1.2487x over previous
#include <cuda_runtime.h>
#include <cuda_fp16.h>
#include <cstdint>

// Problem constants
constexpr int B  = 4;
constexpr int S  = 2048;
constexpr int D  = 1024;
constexpr int H  = 16;
constexpr int DK = 64;
constexpr int M_TOTAL = B * S;   // 8192

constexpr int KA = 2 * D;        // 2048 (w_hi | w_lo)
constexpr size_t ACT_SLOT = (size_t)M_TOTAL * D;       // fp16 single
constexpr size_t W_SLOT   = (size_t)D * KA;            // fp16 hi|lo
constexpr size_t Q_SLOT   = (size_t)B * H * S * 64;    // fp16 single
constexpr size_t KV_SLOT  = (size_t)B * H * S * 64;    // fp16 single

// ---------------------------------------------------------------------------
// Device scratch (allocation-free rule)
// ---------------------------------------------------------------------------
__device__ __half g_ah3[3 * ACT_SLOT];   // q,k,v acts fp16; slot0 reused for attn ctx
__device__ __half g_wh4[4 * W_SLOT];     // w_q,w_k,w_v,w_o fp16 hi/lo
__device__ __half g_qh[Q_SLOT];          // Q head-major fp16 (pre-scaled)
__device__ __half g_kvh[2 * KV_SLOT];    // K, V head-major fp16 single

// ---------------------------------------------------------------------------
// helpers
// ---------------------------------------------------------------------------
__device__ __forceinline__ uint32_t smem_u32(const void* p) {
    uint32_t a;
    asm("{ .reg .u64 t; cvta.to.shared.u64 t, %1; cvt.u32.u64 %0, t; }"
        : "=r"(a) : "l"(p));
    return a;
}
__device__ __forceinline__ void cp16(uint32_t s, const void* g) {
    asm volatile("cp.async.cg.shared.global [%0], [%1], 16;" :: "r"(s), "l"(g));
}
__device__ __forceinline__ void ldmatrix_x4(uint32_t& r0, uint32_t& r1,
                                            uint32_t& r2, uint32_t& r3, uint32_t a) {
    asm volatile("ldmatrix.sync.aligned.m8n8.x4.shared.b16 {%0,%1,%2,%3}, [%4];"
                 : "=r"(r0), "=r"(r1), "=r"(r2), "=r"(r3) : "r"(a));
}
__device__ __forceinline__ void ldmatrix_x4_t(uint32_t& r0, uint32_t& r1,
                                              uint32_t& r2, uint32_t& r3, uint32_t a) {
    asm volatile("ldmatrix.sync.aligned.m8n8.x4.trans.shared.b16 {%0,%1,%2,%3}, [%4];"
                 : "=r"(r0), "=r"(r1), "=r"(r2), "=r"(r3) : "r"(a));
}
__device__ __forceinline__ void mma_f16(float* c, const uint32_t* a, const uint32_t* b) {
    asm volatile("mma.sync.aligned.m16n8k16.row.col.f32.f16.f16.f32 "
                 "{%0,%1,%2,%3},{%4,%5,%6,%7},{%8,%9},{%0,%1,%2,%3};"
                 : "+f"(c[0]), "+f"(c[1]), "+f"(c[2]), "+f"(c[3])
                 : "r"(a[0]), "r"(a[1]), "r"(a[2]), "r"(a[3]), "r"(b[0]), "r"(b[1]));
}
__device__ __forceinline__ uint32_t cvt2h(float phi, float plo) {
    uint32_t r;
    asm("cvt.rn.f16x2.f32 %0, %1, %2;" : "=r"(r) : "f"(phi), "f"(plo));
    return r;
}

// ---------------------------------------------------------------------------
// Conversion kernels
// ---------------------------------------------------------------------------
__global__ __launch_bounds__(256)
void conv_acts(const float* __restrict__ q, const float* __restrict__ k,
               const float* __restrict__ v, __half* __restrict__ Y3)
{
    const int z = blockIdx.y;
    const float* X = (z == 0) ? q : (z == 1) ? k : v;
    __half* Yb = Y3 + (size_t)z * ACT_SLOT;
    const int i = (blockIdx.x * 256 + threadIdx.x) * 4;
    float4 x = *(const float4*)(X + i);
    uint32_t* o = (uint32_t*)(Yb + i);
    o[0] = cvt2h(x.y, x.x);
    o[1] = cvt2h(x.w, x.z);
}

__global__ __launch_bounds__(256)
void conv_ws(const float* __restrict__ wq, const float* __restrict__ wk,
             const float* __restrict__ wv, const float* __restrict__ wo,
             __half* __restrict__ Y4)
{
    const int z = blockIdx.y;
    const float* X = (z == 0) ? wq : (z == 1) ? wk : (z == 2) ? wv : wo;
    __half* Yb = Y4 + (size_t)z * W_SLOT;
    const int i = (blockIdx.x * 256 + threadIdx.x) * 4;
    float4 x = *(const float4*)(X + i);
    const int row = i >> 10;
    const int col = i & (D - 1);
    float xv[4] = {x.x, x.y, x.z, x.w};
    __half h[4];
    float  r[4];
#pragma unroll
    for (int j = 0; j < 4; j++) {
        h[j] = __float2half_rn(xv[j]);
        r[j] = xv[j] - __half2float(h[j]);
    }
    __half* ph = Yb + (size_t)row * KA + col;
    __half* pl = ph + D;
    *(__half2*)(ph)     = __halves2half2(h[0], h[1]);
    *(__half2*)(ph + 2) = __halves2half2(h[2], h[3]);
    *(uint32_t*)(pl)     = cvt2h(r[1], r[0]);
    *(uint32_t*)(pl + 2) = cvt2h(r[3], r[2]);
}

// ---------------------------------------------------------------------------
// fp16 mma.sync GEMM, 2-product: Y = a_f16 · (w_hi + w_lo) + bias
// (round-15 shape, measured ~590 us for 4 GEMMs).
// mode 1 epilogue: all z -> single fp16 head-major [B,H,S,64] (Q scaled).
// ---------------------------------------------------------------------------
constexpr int BKC = 32;
constexpr int NCH = D / BKC;               // 32 chunks
constexpr int TILE_B  = 128 * BKC * 2;     // 8192 B
constexpr int STAGE_B = 3 * TILE_B;        // 24 KB
constexpr int GEMM_SMEM = 3 * STAGE_B;     // 72 KB

__global__ __launch_bounds__(256, 2)
void gemm_tc(const __half* __restrict__ Ab, const __half* __restrict__ Wb,
             const float* __restrict__ bq, const float* __restrict__ bk,
             const float* __restrict__ bv,
             float* __restrict__ Yf, __half* __restrict__ Yq,
             __half* __restrict__ Ykv, int mode)
{
    extern __shared__ char smem[];
    const uint32_t sbase = smem_u32(smem);
    const int tid  = threadIdx.x;
    const int wid  = tid >> 5;
    const int lane = tid & 31;
    const int z = blockIdx.z;
    const int m0 = blockIdx.y * 128;
    const int n0 = blockIdx.x * 128;
    const int wm = (wid >> 2) * 64;
    const int wn = (wid & 3) * 32;

    Ab += (size_t)z * ACT_SLOT;
    Wb += (size_t)z * W_SLOT;
    const float* bias = (z == 0) ? bq : (z == 1) ? bk : bv;
    const float scale = (mode == 1 && z == 0) ? 0.125f : 1.0f;

    float acc[4][4][4];
#pragma unroll
    for (int mi = 0; mi < 4; mi++)
#pragma unroll
        for (int ni = 0; ni < 4; ni++)
#pragma unroll
            for (int r = 0; r < 4; r++) acc[mi][ni][r] = 0.f;

    const int lr = tid >> 1;
    const int lh = tid & 1;

    auto load_chunk = [&](int c) {
        const uint32_t stage = sbase + (uint32_t)(c % 3) * STAGE_B;
        const int kc = c * BKC;
        const int mg = lr >> 3, r8 = lr & 7;
        const __half* ga = Ab + (size_t)(m0 + lr) * D + kc;
        const __half* gw = Wb + (size_t)(n0 + lr) * KA + kc;
#pragma unroll
        for (int j = 0; j < 2; j++) {
            const int kg = lh * 2 + j;
            const uint32_t so = (uint32_t)((kg * 16 + mg) * 128 + r8 * 16);
            cp16(stage + 0 * TILE_B + so, ga + kg * 8);
            cp16(stage + 1 * TILE_B + so, gw + kg * 8);
            cp16(stage + 2 * TILE_B + so, gw + D + kg * 8);
        }
        asm volatile("cp.async.commit_group;");
    };

    load_chunk(0);
    load_chunk(1);

    const int gA = lane >> 3;
    const int rA = lane & 7;

    for (int c = 0; c < NCH; c++) {
        if (c + 1 < NCH) asm volatile("cp.async.wait_group 1;" ::: "memory");
        else             asm volatile("cp.async.wait_group 0;" ::: "memory");
        __syncthreads();
        if (c + 2 < NCH) load_chunk(c + 2);

        const uint32_t stage = sbase + (uint32_t)(c % 3) * STAGE_B;
        const uint32_t aB   = stage;
        const uint32_t whiB = stage + TILE_B;
        const uint32_t wloB = stage + 2 * TILE_B;

#pragma unroll
        for (int ks = 0; ks < 2; ks++) {
            const int kg0 = ks * 2;
            uint32_t af[4][4], bhi[4][2], blo[4][2];
#pragma unroll
            for (int mi = 0; mi < 4; mi++) {
                const int mgB = (wm >> 3) + mi * 2 + (gA & 1);
                const int kgB = kg0 + (gA >> 1);
                const uint32_t off = (uint32_t)((kgB * 16 + mgB) * 128 + rA * 16);
                ldmatrix_x4(af[mi][0], af[mi][1], af[mi][2], af[mi][3], aB + off);
            }
#pragma unroll
            for (int np = 0; np < 2; np++) {
                const int ng  = (wn >> 3) + 2 * np + (gA >> 1);
                const int kgB = kg0 + (gA & 1);
                const uint32_t off = (uint32_t)((kgB * 16 + ng) * 128 + rA * 16);
                ldmatrix_x4(bhi[2*np][0], bhi[2*np][1], bhi[2*np+1][0], bhi[2*np+1][1],
                            whiB + off);
                ldmatrix_x4(blo[2*np][0], blo[2*np][1], blo[2*np+1][0], blo[2*np+1][1],
                            wloB + off);
            }
#pragma unroll
            for (int mi = 0; mi < 4; mi++)
#pragma unroll
                for (int ni = 0; ni < 4; ni++) {
                    mma_f16(acc[mi][ni], af[mi], bhi[ni]);
                    mma_f16(acc[mi][ni], af[mi], blo[ni]);
                }
        }
    }

    // epilogue
#pragma unroll
    for (int mi = 0; mi < 4; mi++) {
#pragma unroll
        for (int ni = 0; ni < 4; ni++) {
            const int m = m0 + wm + mi * 16 + (lane >> 2);
            const int n = n0 + wn + ni * 8 + (lane & 3) * 2;
            const float b0 = __ldg(&bias[n]);
            const float b1 = __ldg(&bias[n + 1]);
            const float v00 = (acc[mi][ni][0] + b0) * scale;
            const float v01 = (acc[mi][ni][1] + b1) * scale;
            const float v10 = (acc[mi][ni][2] + b0) * scale;
            const float v11 = (acc[mi][ni][3] + b1) * scale;
            if (mode == 1) {
                const int h  = n >> 6;
                const int dk = n & (DK - 1);
                __half* arr = (z == 0) ? Yq : (Ykv + (size_t)(z - 1) * KV_SLOT);
#pragma unroll
                for (int rr = 0; rr < 2; rr++) {
                    const int mr = m + rr * 8;
                    const float p0 = rr ? v10 : v00;
                    const float p1 = rr ? v11 : v01;
                    const int bb = mr >> 11;
                    const int s  = mr & (S - 1);
                    const size_t rowi = ((size_t)bb * H + h) * S + s;
                    *(uint32_t*)(arr + rowi * 64 + dk) = cvt2h(p1, p0);
                }
            } else {
                *(float2*)(Yf + (size_t)m * D + n)       = make_float2(v00, v01);
                *(float2*)(Yf + (size_t)(m + 8) * D + n) = make_float2(v10, v11);
            }
        }
    }
}

// ---------------------------------------------------------------------------
// Tensor-core flash attention — all-single-fp16 operands:
//   scores = q_f16 · k_f16,  ctx = p_f16 · v_f16
// ATK=64 key tiles (half the softmax passes), 32 MMAs + 32 LDSM per tile.
// Stage = K(8K)+V(8K) = 16KB == Q smem -> perfect 3-stage recycle; occ 2.
// ---------------------------------------------------------------------------
constexpr int ATQ = 128;
constexpr int ATK = 64;
constexpr int NKT = S / ATK;             // 32
constexpr int Q_SMEM = ATQ * 64 * 2;     // 16384
constexpr int KT_SMEM = ATK * 64 * 2;    // 8192
constexpr int AT_STAGE = 2 * KT_SMEM;    // 16384 == Q_SMEM
constexpr int ATT_SMEM = Q_SMEM + 2 * AT_STAGE;  // 49152

__global__ __launch_bounds__(256, 2)
void attn_mma(const __half* __restrict__ Qh, const __half* __restrict__ Kvh,
              const int* __restrict__ mask, __half* __restrict__ Aout)
{
    extern __shared__ char smem[];
    const uint32_t sq  = smem_u32(smem);
    const uint32_t skv = sq + Q_SMEM;
    const int tid = threadIdx.x, wid = tid >> 5, lane = tid & 31;
    const int b = blockIdx.z, h = blockIdx.y;
    const int q0blk = blockIdx.x * ATQ;
    const size_t headrow = (size_t)(b * H + h) * S;
    const __half* Qg = Qh + (headrow + q0blk) * 64;
    const __half* Kg = Kvh + headrow * 64;
    const __half* Vg = Kvh + KV_SLOT + headrow * 64;
    const int wm = wid * 16;

    auto stage_of = [&](int c) -> uint32_t {
        const int s3 = c % 3;
        return (s3 == 0) ? skv : (s3 == 1) ? (skv + AT_STAGE) : sq;
    };

    auto load_kv = [&](int c) {
        const uint32_t st = stage_of(c);
        const int r = tid & 63, g = tid >> 6;   // 64 rows x 4 thread-groups
        const __half* ks = Kg + (size_t)(c * ATK + r) * 64;
        const __half* vs = Vg + (size_t)(c * ATK + r) * 64;
#pragma unroll
        for (int j = 0; j < 2; j++) {
            const int cg = g * 2 + j;           // 8 col-groups (16B each)
            const uint32_t so = (uint32_t)(((cg * 8 + (r >> 3)) * 8 + (r & 7)) * 16);
            cp16(st + so, ks + cg * 8);
            cp16(st + KT_SMEM + so, vs + cg * 8);
        }
        asm volatile("cp.async.commit_group;");
    };

    // Q tile load: 128 rows x 64 fp16
    {
        const int r = tid & 127, half_ = tid >> 7;
        const __half* src = Qg + (size_t)r * 64;
#pragma unroll
        for (int j = 0; j < 4; j++) {
            const int cg = half_ * 4 + j;
            const uint32_t so = (uint32_t)(((cg * 16 + (r >> 3)) * 8 + (r & 7)) * 16);
            cp16(sq + so, src + cg * 8);
        }
    }
    load_kv(0);
    load_kv(1);

    asm volatile("cp.async.wait_group 1;" ::: "memory");
    __syncthreads();

    const int gA = lane >> 3, rA = lane & 7;

    // Q fragments -> registers (sq becomes KV stage 2 afterwards)
    uint32_t qh[4][4];
#pragma unroll
    for (int kk = 0; kk < 4; kk++) {
        const int rg = (wm >> 3) + (gA & 1);
        const int cgh = 2 * kk + (gA >> 1);
        ldmatrix_x4(qh[kk][0], qh[kk][1], qh[kk][2], qh[kk][3],
                    sq + (uint32_t)(((cgh * 16 + rg) * 8 + rA) * 16));
    }
    __syncthreads();

    float o[8][4];
#pragma unroll
    for (int ng = 0; ng < 8; ng++)
#pragma unroll
        for (int r = 0; r < 4; r++) o[ng][r] = 0.f;
    float m0 = -1e30f, m1 = -1e30f, l0 = 0.f, l1 = 0.f;

    const int r0l = lane >> 2, c0l = (lane & 3) * 2;
    const int qg0 = q0blk + wm + r0l;
    const int* mr0 = mask + ((size_t)b * S + qg0) * S + c0l;
    const int* mr1 = mr0 + 8 * S;

#pragma unroll 1
    for (int c = 0; c < NKT; c++) {
        if (c + 1 < NKT) asm volatile("cp.async.wait_group 1;" ::: "memory");
        else             asm volatile("cp.async.wait_group 0;" ::: "memory");
        __syncthreads();
        if (c + 2 < NKT) load_kv(c + 2);

        const uint32_t kb_ = stage_of(c);
        const uint32_t vb_ = kb_ + KT_SMEM;

        // ---- scores: q_f16 · k_f16  (64 keys -> sc[8][4]) ----
        float sc[8][4];
#pragma unroll
        for (int ng = 0; ng < 8; ng++)
#pragma unroll
            for (int r = 0; r < 4; r++) sc[ng][r] = 0.f;

#pragma unroll
        for (int ng = 0; ng < 8; ng += 2) {
#pragma unroll
            for (int kk = 0; kk < 4; kk++) {
                uint32_t kh[4];
                const int rg = ng + (gA >> 1);          // key row-group 0..7
                const int cg = 2 * kk + (gA & 1);       // dk col-group 0..7
                ldmatrix_x4(kh[0], kh[1], kh[2], kh[3],
                            kb_ + (uint32_t)(((cg * 8 + rg) * 8 + rA) * 16));
                mma_f16(sc[ng],     qh[kk], kh + 0);
                mma_f16(sc[ng + 1], qh[kk], kh + 2);
            }
        }

        // ---- mask ----
        const int koff = c * ATK;
#pragma unroll
        for (int ng = 0; ng < 8; ng++) {
            const int2 mA = *(const int2*)(mr0 + koff + ng * 8);
            const int2 mB = *(const int2*)(mr1 + koff + ng * 8);
            if (mA.x == 0) sc[ng][0] = -1e9f;
            if (mA.y == 0) sc[ng][1] = -1e9f;
            if (mB.x == 0) sc[ng][2] = -1e9f;
            if (mB.y == 0) sc[ng][3] = -1e9f;
        }

        // ---- online softmax ----
        float mx0 = sc[0][0], mx1 = sc[0][2];
#pragma unroll
        for (int ng = 0; ng < 8; ng++) {
            mx0 = fmaxf(mx0, fmaxf(sc[ng][0], sc[ng][1]));
            mx1 = fmaxf(mx1, fmaxf(sc[ng][2], sc[ng][3]));
        }
        mx0 = fmaxf(mx0, __shfl_xor_sync(0xffffffffu, mx0, 1));
        mx0 = fmaxf(mx0, __shfl_xor_sync(0xffffffffu, mx0, 2));
        mx1 = fmaxf(mx1, __shfl_xor_sync(0xffffffffu, mx1, 1));
        mx1 = fmaxf(mx1, __shfl_xor_sync(0xffffffffu, mx1, 2));

        const float mn0 = fmaxf(m0, mx0);
        const float mn1 = fmaxf(m1, mx1);
        const float cr0 = __expf(m0 - mn0);
        const float cr1 = __expf(m1 - mn1);
#pragma unroll
        for (int ng = 0; ng < 8; ng++) {
            o[ng][0] *= cr0; o[ng][1] *= cr0;
            o[ng][2] *= cr1; o[ng][3] *= cr1;
        }

        // ---- exp + P·V fused (P single fp16), kp-outer (4 kp of 16 keys) ----
        float rs0 = 0.f, rs1 = 0.f;
#pragma unroll
        for (int kp = 0; kp < 4; kp++) {
            const float p00 = __expf(sc[2*kp][0]   - mn0);
            const float p01 = __expf(sc[2*kp][1]   - mn0);
            const float p10 = __expf(sc[2*kp][2]   - mn1);
            const float p11 = __expf(sc[2*kp][3]   - mn1);
            const float p20 = __expf(sc[2*kp+1][0] - mn0);
            const float p21 = __expf(sc[2*kp+1][1] - mn0);
            const float p30 = __expf(sc[2*kp+1][2] - mn1);
            const float p31 = __expf(sc[2*kp+1][3] - mn1);
            rs0 += (p00 + p01) + (p20 + p21);
            rs1 += (p10 + p11) + (p30 + p31);
            uint32_t ph[4];
            ph[0] = cvt2h(p01, p00);
            ph[1] = cvt2h(p11, p10);
            ph[2] = cvt2h(p21, p20);
            ph[3] = cvt2h(p31, p30);

            const int rg = 2 * kp + (gA & 1);   // key row-group 0..7
#pragma unroll
            for (int ng = 0; ng < 8; ng += 2) {
                const int cg = ng + (gA >> 1);  // dk col-group 0..7
                uint32_t vh[4];
                ldmatrix_x4_t(vh[0], vh[1], vh[2], vh[3],
                              vb_ + (uint32_t)(((cg * 8 + rg) * 8 + rA) * 16));
                mma_f16(o[ng],     ph, vh + 0);
                mma_f16(o[ng + 1], ph, vh + 2);
            }
        }
        rs0 += __shfl_xor_sync(0xffffffffu, rs0, 1);
        rs0 += __shfl_xor_sync(0xffffffffu, rs0, 2);
        rs1 += __shfl_xor_sync(0xffffffffu, rs1, 1);
        rs1 += __shfl_xor_sync(0xffffffffu, rs1, 2);
        l0 = l0 * cr0 + rs0;
        l1 = l1 * cr1 + rs1;
        m0 = mn0; m1 = mn1;
    }

    // ---- epilogue: ctx fp16 single into the O-proj A buffer ----
    const float inv0 = 1.f / l0;
    const float inv1 = 1.f / l1;
    __half* dst0 = Aout + (size_t)(b * S + qg0) * D + h * DK + c0l;
    __half* dst1 = dst0 + (size_t)8 * D;
#pragma unroll
    for (int ng = 0; ng < 8; ng++) {
        *(uint32_t*)(dst0 + ng * 8) = cvt2h(o[ng][1] * inv0, o[ng][0] * inv0);
        *(uint32_t*)(dst1 + ng * 8) = cvt2h(o[ng][3] * inv1, o[ng][2] * inv1);
    }
}

// ---------------------------------------------------------------------------
// launch
// ---------------------------------------------------------------------------
extern "C" void kernel_launch(void* const* d_in, const int* in_sizes, int n_in,
                              void* d_out, int out_size)
{
    const float* query = (const float*)d_in[0];
    const float* key_  = (const float*)d_in[1];
    const float* value = (const float*)d_in[2];
    const int*   amask = (const int*)  d_in[3];
    const float* w_q = (const float*)d_in[4];
    const float* b_q = (const float*)d_in[5];
    const float* w_k = (const float*)d_in[6];
    const float* b_k = (const float*)d_in[7];
    const float* w_v = (const float*)d_in[8];
    const float* b_v = (const float*)d_in[9];
    const float* w_o = (const float*)d_in[10];
    const float* b_o = (const float*)d_in[11];
    float* out = (float*)d_out;

    __half *gah3, *gwh4, *gqh, *gkvh;
    cudaGetSymbolAddress((void**)&gah3, g_ah3);
    cudaGetSymbolAddress((void**)&gwh4, g_wh4);
    cudaGetSymbolAddress((void**)&gqh,  g_qh);
    cudaGetSymbolAddress((void**)&gkvh, g_kvh);

    cudaFuncSetAttribute(gemm_tc, cudaFuncAttributeMaxDynamicSharedMemorySize, GEMM_SMEM);
    cudaFuncSetAttribute(attn_mma, cudaFuncAttributeMaxDynamicSharedMemorySize, ATT_SMEM);

    conv_acts<<<dim3(M_TOTAL * D / (4 * 256), 3), 256>>>(query, key_, value, gah3);
    conv_ws  <<<dim3(D * D / (4 * 256), 4), 256>>>(w_q, w_k, w_v, w_o, gwh4);

    gemm_tc<<<dim3(D / 128, M_TOTAL / 128, 3), 256, GEMM_SMEM>>>(
        gah3, gwh4, b_q, b_k, b_v, nullptr, gqh, gkvh, 1);

    attn_mma<<<dim3(S / ATQ, H, B), 256, ATT_SMEM>>>(gqh, gkvh, amask, gah3);

    gemm_tc<<<dim3(D / 128, M_TOTAL / 128, 1), 256, GEMM_SMEM>>>(
        gah3, gwh4 + 3 * W_SLOT, b_o, b_o, b_o, out, nullptr, nullptr, 0);
}

// round 17
// speedup vs baseline: 2.2066x; 1.2712x over previous
#include <cuda_runtime.h>
#include <cuda_fp16.h>
#include <cstdint>

// Problem constants
constexpr int B  = 4;
constexpr int S  = 2048;
constexpr int D  = 1024;
constexpr int H  = 16;
constexpr int DK = 64;
constexpr int M_TOTAL = B * S;   // 8192

constexpr size_t ACT_SLOT = (size_t)M_TOTAL * D;       // fp16 single
constexpr size_t W_SLOT   = (size_t)D * D;             // fp16 single
constexpr size_t Q_SLOT   = (size_t)B * H * S * 64;    // fp16 single
constexpr size_t KV_SLOT  = (size_t)B * H * S * 64;    // fp16 single

// ---------------------------------------------------------------------------
// Device scratch (allocation-free rule)
// ---------------------------------------------------------------------------
__device__ __half g_ah3[3 * ACT_SLOT];   // q,k,v acts fp16; slot0 reused for attn ctx
__device__ __half g_wh4[4 * W_SLOT];     // w_q,w_k,w_v,w_o fp16 single
__device__ __half g_qh[Q_SLOT];          // Q head-major fp16 (pre-scaled)
__device__ __half g_kvh[2 * KV_SLOT];    // K, V head-major fp16 single

// ---------------------------------------------------------------------------
// helpers
// ---------------------------------------------------------------------------
__device__ __forceinline__ uint32_t smem_u32(const void* p) {
    uint32_t a;
    asm("{ .reg .u64 t; cvta.to.shared.u64 t, %1; cvt.u32.u64 %0, t; }"
        : "=r"(a) : "l"(p));
    return a;
}
__device__ __forceinline__ void cp16(uint32_t s, const void* g) {
    asm volatile("cp.async.cg.shared.global [%0], [%1], 16;" :: "r"(s), "l"(g));
}
__device__ __forceinline__ void ldmatrix_x4(uint32_t& r0, uint32_t& r1,
                                            uint32_t& r2, uint32_t& r3, uint32_t a) {
    asm volatile("ldmatrix.sync.aligned.m8n8.x4.shared.b16 {%0,%1,%2,%3}, [%4];"
                 : "=r"(r0), "=r"(r1), "=r"(r2), "=r"(r3) : "r"(a));
}
__device__ __forceinline__ void ldmatrix_x4_t(uint32_t& r0, uint32_t& r1,
                                              uint32_t& r2, uint32_t& r3, uint32_t a) {
    asm volatile("ldmatrix.sync.aligned.m8n8.x4.trans.shared.b16 {%0,%1,%2,%3}, [%4];"
                 : "=r"(r0), "=r"(r1), "=r"(r2), "=r"(r3) : "r"(a));
}
__device__ __forceinline__ void mma_f16(float* c, const uint32_t* a, const uint32_t* b) {
    asm volatile("mma.sync.aligned.m16n8k16.row.col.f32.f16.f16.f32 "
                 "{%0,%1,%2,%3},{%4,%5,%6,%7},{%8,%9},{%0,%1,%2,%3};"
                 : "+f"(c[0]), "+f"(c[1]), "+f"(c[2]), "+f"(c[3])
                 : "r"(a[0]), "r"(a[1]), "r"(a[2]), "r"(a[3]), "r"(b[0]), "r"(b[1]));
}
__device__ __forceinline__ uint32_t cvt2h(float phi, float plo) {
    uint32_t r;
    asm("cvt.rn.f16x2.f32 %0, %1, %2;" : "=r"(r) : "f"(phi), "f"(plo));
    return r;
}

// ---------------------------------------------------------------------------
// Conversion kernels: fp32 -> fp16 single
// ---------------------------------------------------------------------------
__global__ __launch_bounds__(256)
void conv_acts(const float* __restrict__ q, const float* __restrict__ k,
               const float* __restrict__ v, __half* __restrict__ Y3)
{
    const int z = blockIdx.y;
    const float* X = (z == 0) ? q : (z == 1) ? k : v;
    __half* Yb = Y3 + (size_t)z * ACT_SLOT;
    const int i = (blockIdx.x * 256 + threadIdx.x) * 4;
    float4 x = *(const float4*)(X + i);
    uint32_t* o = (uint32_t*)(Yb + i);
    o[0] = cvt2h(x.y, x.x);
    o[1] = cvt2h(x.w, x.z);
}

__global__ __launch_bounds__(256)
void conv_ws(const float* __restrict__ wq, const float* __restrict__ wk,
             const float* __restrict__ wv, const float* __restrict__ wo,
             __half* __restrict__ Y4)
{
    const int z = blockIdx.y;
    const float* X = (z == 0) ? wq : (z == 1) ? wk : (z == 2) ? wv : wo;
    __half* Yb = Y4 + (size_t)z * W_SLOT;
    const int i = (blockIdx.x * 256 + threadIdx.x) * 4;
    float4 x = *(const float4*)(X + i);
    uint32_t* o = (uint32_t*)(Yb + i);
    o[0] = cvt2h(x.y, x.x);
    o[1] = cvt2h(x.w, x.z);
}

// ---------------------------------------------------------------------------
// fp16 mma.sync GEMM, single-product: Y = a_f16 · w_f16 + bias
// 128x128 CTA, 256 threads / 8 warps, warp tile 64x32, 3-stage pipeline.
// Stage = A(8K) + W(8K) = 16 KB; 48 KB total; occupancy 2.
// ---------------------------------------------------------------------------
constexpr int BKC = 32;
constexpr int NCH = D / BKC;               // 32 chunks
constexpr int TILE_B  = 128 * BKC * 2;     // 8192 B
constexpr int STAGE_B = 2 * TILE_B;        // 16 KB
constexpr int GEMM_SMEM = 3 * STAGE_B;     // 48 KB

__global__ __launch_bounds__(256, 2)
void gemm_tc(const __half* __restrict__ Ab, const __half* __restrict__ Wb,
             const float* __restrict__ bq, const float* __restrict__ bk,
             const float* __restrict__ bv,
             float* __restrict__ Yf, __half* __restrict__ Yq,
             __half* __restrict__ Ykv, int mode)
{
    extern __shared__ char smem[];
    const uint32_t sbase = smem_u32(smem);
    const int tid  = threadIdx.x;
    const int wid  = tid >> 5;
    const int lane = tid & 31;
    const int z = blockIdx.z;
    const int m0 = blockIdx.y * 128;
    const int n0 = blockIdx.x * 128;
    const int wm = (wid >> 2) * 64;
    const int wn = (wid & 3) * 32;

    Ab += (size_t)z * ACT_SLOT;
    Wb += (size_t)z * W_SLOT;
    const float* bias = (z == 0) ? bq : (z == 1) ? bk : bv;
    const float scale = (mode == 1 && z == 0) ? 0.125f : 1.0f;

    float acc[4][4][4];
#pragma unroll
    for (int mi = 0; mi < 4; mi++)
#pragma unroll
        for (int ni = 0; ni < 4; ni++)
#pragma unroll
            for (int r = 0; r < 4; r++) acc[mi][ni][r] = 0.f;

    const int lr = tid >> 1;
    const int lh = tid & 1;

    auto load_chunk = [&](int c) {
        const uint32_t stage = sbase + (uint32_t)(c % 3) * STAGE_B;
        const int kc = c * BKC;
        const int mg = lr >> 3, r8 = lr & 7;
        const __half* ga = Ab + (size_t)(m0 + lr) * D + kc;
        const __half* gw = Wb + (size_t)(n0 + lr) * D + kc;
#pragma unroll
        for (int j = 0; j < 2; j++) {
            const int kg = lh * 2 + j;
            const uint32_t so = (uint32_t)((kg * 16 + mg) * 128 + r8 * 16);
            cp16(stage + so, ga + kg * 8);                 // A
            cp16(stage + TILE_B + so, gw + kg * 8);        // W
        }
        asm volatile("cp.async.commit_group;");
    };

    load_chunk(0);
    load_chunk(1);

    const int gA = lane >> 3;
    const int rA = lane & 7;

    for (int c = 0; c < NCH; c++) {
        if (c + 1 < NCH) asm volatile("cp.async.wait_group 1;" ::: "memory");
        else             asm volatile("cp.async.wait_group 0;" ::: "memory");
        __syncthreads();
        if (c + 2 < NCH) load_chunk(c + 2);

        const uint32_t stage = sbase + (uint32_t)(c % 3) * STAGE_B;
        const uint32_t aB = stage;
        const uint32_t wB = stage + TILE_B;

#pragma unroll
        for (int ks = 0; ks < 2; ks++) {
            const int kg0 = ks * 2;
            uint32_t af[4][4], bf[4][2];
#pragma unroll
            for (int mi = 0; mi < 4; mi++) {
                const int mgB = (wm >> 3) + mi * 2 + (gA & 1);
                const int kgB = kg0 + (gA >> 1);
                const uint32_t off = (uint32_t)((kgB * 16 + mgB) * 128 + rA * 16);
                ldmatrix_x4(af[mi][0], af[mi][1], af[mi][2], af[mi][3], aB + off);
            }
#pragma unroll
            for (int np = 0; np < 2; np++) {
                const int ng  = (wn >> 3) + 2 * np + (gA >> 1);
                const int kgB = kg0 + (gA & 1);
                const uint32_t off = (uint32_t)((kgB * 16 + ng) * 128 + rA * 16);
                ldmatrix_x4(bf[2*np][0], bf[2*np][1], bf[2*np+1][0], bf[2*np+1][1],
                            wB + off);
            }
#pragma unroll
            for (int mi = 0; mi < 4; mi++)
#pragma unroll
                for (int ni = 0; ni < 4; ni++)
                    mma_f16(acc[mi][ni], af[mi], bf[ni]);
        }
    }

    // epilogue
#pragma unroll
    for (int mi = 0; mi < 4; mi++) {
#pragma unroll
        for (int ni = 0; ni < 4; ni++) {
            const int m = m0 + wm + mi * 16 + (lane >> 2);
            const int n = n0 + wn + ni * 8 + (lane & 3) * 2;
            const float b0 = __ldg(&bias[n]);
            const float b1 = __ldg(&bias[n + 1]);
            const float v00 = (acc[mi][ni][0] + b0) * scale;
            const float v01 = (acc[mi][ni][1] + b1) * scale;
            const float v10 = (acc[mi][ni][2] + b0) * scale;
            const float v11 = (acc[mi][ni][3] + b1) * scale;
            if (mode == 1) {
                const int h  = n >> 6;
                const int dk = n & (DK - 1);
                __half* arr = (z == 0) ? Yq : (Ykv + (size_t)(z - 1) * KV_SLOT);
#pragma unroll
                for (int rr = 0; rr < 2; rr++) {
                    const int mr = m + rr * 8;
                    const float p0 = rr ? v10 : v00;
                    const float p1 = rr ? v11 : v01;
                    const int bb = mr >> 11;
                    const int s  = mr & (S - 1);
                    const size_t rowi = ((size_t)bb * H + h) * S + s;
                    *(uint32_t*)(arr + rowi * 64 + dk) = cvt2h(p1, p0);
                }
            } else {
                *(float2*)(Yf + (size_t)m * D + n)       = make_float2(v00, v01);
                *(float2*)(Yf + (size_t)(m + 8) * D + n) = make_float2(v10, v11);
            }
        }
    }
}

// ---------------------------------------------------------------------------
// Tensor-core flash attention — all-single-fp16 (round-16 shape, 426 us).
// ATK=64 key tiles, occ 2, 3-stage recycle of Q smem.
// ---------------------------------------------------------------------------
constexpr int ATQ = 128;
constexpr int ATK = 64;
constexpr int NKT = S / ATK;             // 32
constexpr int Q_SMEM = ATQ * 64 * 2;     // 16384
constexpr int KT_SMEM = ATK * 64 * 2;    // 8192
constexpr int AT_STAGE = 2 * KT_SMEM;    // 16384 == Q_SMEM
constexpr int ATT_SMEM = Q_SMEM + 2 * AT_STAGE;  // 49152

__global__ __launch_bounds__(256, 2)
void attn_mma(const __half* __restrict__ Qh, const __half* __restrict__ Kvh,
              const int* __restrict__ mask, __half* __restrict__ Aout)
{
    extern __shared__ char smem[];
    const uint32_t sq  = smem_u32(smem);
    const uint32_t skv = sq + Q_SMEM;
    const int tid = threadIdx.x, wid = tid >> 5, lane = tid & 31;
    const int b = blockIdx.z, h = blockIdx.y;
    const int q0blk = blockIdx.x * ATQ;
    const size_t headrow = (size_t)(b * H + h) * S;
    const __half* Qg = Qh + (headrow + q0blk) * 64;
    const __half* Kg = Kvh + headrow * 64;
    const __half* Vg = Kvh + KV_SLOT + headrow * 64;
    const int wm = wid * 16;

    auto stage_of = [&](int c) -> uint32_t {
        const int s3 = c % 3;
        return (s3 == 0) ? skv : (s3 == 1) ? (skv + AT_STAGE) : sq;
    };

    auto load_kv = [&](int c) {
        const uint32_t st = stage_of(c);
        const int r = tid & 63, g = tid >> 6;
        const __half* ks = Kg + (size_t)(c * ATK + r) * 64;
        const __half* vs = Vg + (size_t)(c * ATK + r) * 64;
#pragma unroll
        for (int j = 0; j < 2; j++) {
            const int cg = g * 2 + j;
            const uint32_t so = (uint32_t)(((cg * 8 + (r >> 3)) * 8 + (r & 7)) * 16);
            cp16(st + so, ks + cg * 8);
            cp16(st + KT_SMEM + so, vs + cg * 8);
        }
        asm volatile("cp.async.commit_group;");
    };

    // Q tile load
    {
        const int r = tid & 127, half_ = tid >> 7;
        const __half* src = Qg + (size_t)r * 64;
#pragma unroll
        for (int j = 0; j < 4; j++) {
            const int cg = half_ * 4 + j;
            const uint32_t so = (uint32_t)(((cg * 16 + (r >> 3)) * 8 + (r & 7)) * 16);
            cp16(sq + so, src + cg * 8);
        }
    }
    load_kv(0);
    load_kv(1);

    asm volatile("cp.async.wait_group 1;" ::: "memory");
    __syncthreads();

    const int gA = lane >> 3, rA = lane & 7;

    // Q fragments -> registers
    uint32_t qh[4][4];
#pragma unroll
    for (int kk = 0; kk < 4; kk++) {
        const int rg = (wm >> 3) + (gA & 1);
        const int cgh = 2 * kk + (gA >> 1);
        ldmatrix_x4(qh[kk][0], qh[kk][1], qh[kk][2], qh[kk][3],
                    sq + (uint32_t)(((cgh * 16 + rg) * 8 + rA) * 16));
    }
    __syncthreads();

    float o[8][4];
#pragma unroll
    for (int ng = 0; ng < 8; ng++)
#pragma unroll
        for (int r = 0; r < 4; r++) o[ng][r] = 0.f;
    float m0 = -1e30f, m1 = -1e30f, l0 = 0.f, l1 = 0.f;

    const int r0l = lane >> 2, c0l = (lane & 3) * 2;
    const int qg0 = q0blk + wm + r0l;
    const int* mr0 = mask + ((size_t)b * S + qg0) * S + c0l;
    const int* mr1 = mr0 + 8 * S;

#pragma unroll 1
    for (int c = 0; c < NKT; c++) {
        if (c + 1 < NKT) asm volatile("cp.async.wait_group 1;" ::: "memory");
        else             asm volatile("cp.async.wait_group 0;" ::: "memory");
        __syncthreads();
        if (c + 2 < NKT) load_kv(c + 2);

        const uint32_t kb_ = stage_of(c);
        const uint32_t vb_ = kb_ + KT_SMEM;

        // ---- scores ----
        float sc[8][4];
#pragma unroll
        for (int ng = 0; ng < 8; ng++)
#pragma unroll
            for (int r = 0; r < 4; r++) sc[ng][r] = 0.f;

#pragma unroll
        for (int ng = 0; ng < 8; ng += 2) {
#pragma unroll
            for (int kk = 0; kk < 4; kk++) {
                uint32_t kh[4];
                const int rg = ng + (gA >> 1);
                const int cg = 2 * kk + (gA & 1);
                ldmatrix_x4(kh[0], kh[1], kh[2], kh[3],
                            kb_ + (uint32_t)(((cg * 8 + rg) * 8 + rA) * 16));
                mma_f16(sc[ng],     qh[kk], kh + 0);
                mma_f16(sc[ng + 1], qh[kk], kh + 2);
            }
        }

        // ---- mask ----
        const int koff = c * ATK;
#pragma unroll
        for (int ng = 0; ng < 8; ng++) {
            const int2 mA = *(const int2*)(mr0 + koff + ng * 8);
            const int2 mB = *(const int2*)(mr1 + koff + ng * 8);
            if (mA.x == 0) sc[ng][0] = -1e9f;
            if (mA.y == 0) sc[ng][1] = -1e9f;
            if (mB.x == 0) sc[ng][2] = -1e9f;
            if (mB.y == 0) sc[ng][3] = -1e9f;
        }

        // ---- online softmax ----
        float mx0 = sc[0][0], mx1 = sc[0][2];
#pragma unroll
        for (int ng = 0; ng < 8; ng++) {
            mx0 = fmaxf(mx0, fmaxf(sc[ng][0], sc[ng][1]));
            mx1 = fmaxf(mx1, fmaxf(sc[ng][2], sc[ng][3]));
        }
        mx0 = fmaxf(mx0, __shfl_xor_sync(0xffffffffu, mx0, 1));
        mx0 = fmaxf(mx0, __shfl_xor_sync(0xffffffffu, mx0, 2));
        mx1 = fmaxf(mx1, __shfl_xor_sync(0xffffffffu, mx1, 1));
        mx1 = fmaxf(mx1, __shfl_xor_sync(0xffffffffu, mx1, 2));

        const float mn0 = fmaxf(m0, mx0);
        const float mn1 = fmaxf(m1, mx1);
        const float cr0 = __expf(m0 - mn0);
        const float cr1 = __expf(m1 - mn1);
#pragma unroll
        for (int ng = 0; ng < 8; ng++) {
            o[ng][0] *= cr0; o[ng][1] *= cr0;
            o[ng][2] *= cr1; o[ng][3] *= cr1;
        }

        // ---- exp + P·V fused, kp-outer ----
        float rs0 = 0.f, rs1 = 0.f;
#pragma unroll
        for (int kp = 0; kp < 4; kp++) {
            const float p00 = __expf(sc[2*kp][0]   - mn0);
            const float p01 = __expf(sc[2*kp][1]   - mn0);
            const float p10 = __expf(sc[2*kp][2]   - mn1);
            const float p11 = __expf(sc[2*kp][3]   - mn1);
            const float p20 = __expf(sc[2*kp+1][0] - mn0);
            const float p21 = __expf(sc[2*kp+1][1] - mn0);
            const float p30 = __expf(sc[2*kp+1][2] - mn1);
            const float p31 = __expf(sc[2*kp+1][3] - mn1);
            rs0 += (p00 + p01) + (p20 + p21);
            rs1 += (p10 + p11) + (p30 + p31);
            uint32_t ph[4];
            ph[0] = cvt2h(p01, p00);
            ph[1] = cvt2h(p11, p10);
            ph[2] = cvt2h(p21, p20);
            ph[3] = cvt2h(p31, p30);

            const int rg = 2 * kp + (gA & 1);
#pragma unroll
            for (int ng = 0; ng < 8; ng += 2) {
                const int cg = ng + (gA >> 1);
                uint32_t vh[4];
                ldmatrix_x4_t(vh[0], vh[1], vh[2], vh[3],
                              vb_ + (uint32_t)(((cg * 8 + rg) * 8 + rA) * 16));
                mma_f16(o[ng],     ph, vh + 0);
                mma_f16(o[ng + 1], ph, vh + 2);
            }
        }
        rs0 += __shfl_xor_sync(0xffffffffu, rs0, 1);
        rs0 += __shfl_xor_sync(0xffffffffu, rs0, 2);
        rs1 += __shfl_xor_sync(0xffffffffu, rs1, 1);
        rs1 += __shfl_xor_sync(0xffffffffu, rs1, 2);
        l0 = l0 * cr0 + rs0;
        l1 = l1 * cr1 + rs1;
        m0 = mn0; m1 = mn1;
    }

    // ---- epilogue: ctx fp16 single into the O-proj A buffer ----
    const float inv0 = 1.f / l0;
    const float inv1 = 1.f / l1;
    __half* dst0 = Aout + (size_t)(b * S + qg0) * D + h * DK + c0l;
    __half* dst1 = dst0 + (size_t)8 * D;
#pragma unroll
    for (int ng = 0; ng < 8; ng++) {
        *(uint32_t*)(dst0 + ng * 8) = cvt2h(o[ng][1] * inv0, o[ng][0] * inv0);
        *(uint32_t*)(dst1 + ng * 8) = cvt2h(o[ng][3] * inv1, o[ng][2] * inv1);
    }
}

// ---------------------------------------------------------------------------
// launch
// ---------------------------------------------------------------------------
extern "C" void kernel_launch(void* const* d_in, const int* in_sizes, int n_in,
                              void* d_out, int out_size)
{
    const float* query = (const float*)d_in[0];
    const float* key_  = (const float*)d_in[1];
    const float* value = (const float*)d_in[2];
    const int*   amask = (const int*)  d_in[3];
    const float* w_q = (const float*)d_in[4];
    const float* b_q = (const float*)d_in[5];
    const float* w_k = (const float*)d_in[6];
    const float* b_k = (const float*)d_in[7];
    const float* w_v = (const float*)d_in[8];
    const float* b_v = (const float*)d_in[9];
    const float* w_o = (const float*)d_in[10];
    const float* b_o = (const float*)d_in[11];
    float* out = (float*)d_out;

    __half *gah3, *gwh4, *gqh, *gkvh;
    cudaGetSymbolAddress((void**)&gah3, g_ah3);
    cudaGetSymbolAddress((void**)&gwh4, g_wh4);
    cudaGetSymbolAddress((void**)&gqh,  g_qh);
    cudaGetSymbolAddress((void**)&gkvh, g_kvh);

    cudaFuncSetAttribute(gemm_tc, cudaFuncAttributeMaxDynamicSharedMemorySize, GEMM_SMEM);
    cudaFuncSetAttribute(attn_mma, cudaFuncAttributeMaxDynamicSharedMemorySize, ATT_SMEM);

    conv_acts<<<dim3(M_TOTAL * D / (4 * 256), 3), 256>>>(query, key_, value, gah3);
    conv_ws  <<<dim3(D * D / (4 * 256), 4), 256>>>(w_q, w_k, w_v, w_o, gwh4);

    gemm_tc<<<dim3(D / 128, M_TOTAL / 128, 3), 256, GEMM_SMEM>>>(
        gah3, gwh4, b_q, b_k, b_v, nullptr, gqh, gkvh, 1);

    attn_mma<<<dim3(S / ATQ, H, B), 256, ATT_SMEM>>>(gqh, gkvh, amask, gah3);

    gemm_tc<<<dim3(D / 128, M_TOTAL / 128, 1), 256, GEMM_SMEM>>>(
        gah3, gwh4 + 3 * W_SLOT, b_o, b_o, b_o, out, nullptr, nullptr, 0);
}